// round 4
// baseline (speedup 1.0000x reference)
#include <cuda_runtime.h>
#include <cstdint>
#include <cstddef>

#define MAXNNZ 40
#define BG 256
#define SLICE 25165824UL   // 768*256*128 floats (largest N*B*F slab)

// ---------------- static scratch (no allocation allowed) ----------------
__device__ float g_A[SLICE];                 // ping buffer (N,B,F)
__device__ float g_B[SLICE];                 // pong buffer
__device__ float g_Z[3*SLICE];               // Chebyshev terms x1,x2,x3
__device__ float g_S3[768*256*64];           // skip s3
__device__ float g_S2[192*256*128];          // skip s2
__device__ float g_S1[48*256*256];           // skip s1
__device__ int   g_cidx[4*768*MAXNNZ];       // CSR-ELL col indices per level
__device__ float g_cval[4*768*MAXNNZ];       // CSR-ELL values
__device__ int   g_cnnz[4*768];              // per-row nnz
__device__ float g_sum[256];                 // BN channel sums
__device__ float g_sq[256];                  // BN channel sum-of-squares

// ---------------- kernels ----------------

// Extract ELL sparse structure from dense scaled Laplacian (exact zeros off-support).
__global__ void build_csr_k(const float* __restrict__ L, int N,
                            int* __restrict__ idx, float* __restrict__ val,
                            int* __restrict__ nnz) {
    int n = blockIdx.x * blockDim.x + threadIdx.x;
    if (n >= N) return;
    int c = 0;
    for (int m = 0; m < N; m++) {
        float v = L[n * N + m];
        if (v != 0.0f && c < MAXNNZ) {
            idx[n * MAXNNZ + c] = m;
            val[n * MAXNNZ + c] = v;
            c++;
        }
    }
    nnz[n] = c;
}

// x (4,8,8,8,768) -> A layout (n, bg, c) with bg = b0*64 + hw
__global__ void transpose_in_k(const float* __restrict__ x, float* __restrict__ A) {
    int t = blockIdx.x * blockDim.x + threadIdx.x;  // 1,572,864 total
    int n = t % 768;
    int r = t / 768;
    int hw = r & 63; r >>= 6;
    int c = r & 7;  int b0 = r >> 3;
    A[((size_t)n * BG + (size_t)b0 * 64 + hw) * 8 + c] = x[t];
}

// Z[row, :] = alpha * sum_j L[row, col_j] * X[col_j, :]  (- S[row, :] if S)
// Columns = B*F floats, processed as float4. cols4 is always a multiple of 256.
__global__ void spmm_k(const int* __restrict__ idx, const float* __restrict__ val,
                       const int* __restrict__ nnz, int cols4,
                       const float4* __restrict__ X, float4* __restrict__ Z,
                       float alpha, const float4* __restrict__ S) {
    int row = blockIdx.y;
    int c = blockIdx.x * blockDim.x + threadIdx.x;
    __shared__ int   si[MAXNNZ];
    __shared__ float sv[MAXNNZ];
    __shared__ int   sn;
    int tid = threadIdx.x;
    if (tid < MAXNNZ) { si[tid] = idx[row * MAXNNZ + tid]; sv[tid] = val[row * MAXNNZ + tid]; }
    if (tid == 0) sn = nnz[row];
    __syncthreads();
    float4 acc = make_float4(0.f, 0.f, 0.f, 0.f);
    int nn = sn;
    #pragma unroll 4
    for (int j = 0; j < nn; j++) {
        float v = sv[j];
        float4 xv = __ldg(&X[(size_t)si[j] * cols4 + c]);
        acc.x += v * xv.x; acc.y += v * xv.y; acc.z += v * xv.z; acc.w += v * xv.w;
    }
    size_t o = (size_t)row * cols4 + c;
    float4 out;
    if (S) {
        float4 s = S[o];
        out = make_float4(alpha * acc.x - s.x, alpha * acc.y - s.y,
                          alpha * acc.z - s.z, alpha * acc.w - s.w);
    } else {
        out = make_float4(alpha * acc.x, alpha * acc.y, alpha * acc.z, alpha * acc.w);
    }
    Z[o] = out;
}

// C(M x No) = U(M x 4F) @ W(4F x No); U segments: seg0 = A0, seg k = Zb + (k-1)*SLICE.
// All segment matrices are (M x F) row-major.  M % 64 == 0, F % 8 == 0.
__global__ __launch_bounds__(256) void stageb_k(
        const float* __restrict__ A0, const float* __restrict__ Zb,
        const float* __restrict__ W, float* __restrict__ C,
        int M, int F, int No) {
    __shared__ float As[8][64];
    __shared__ float Ws[8][64];
    int tid = threadIdx.x;
    int m0 = blockIdx.x * 64, n0 = blockIdx.y * 64;
    int tr = tid >> 4, tc = tid & 15;
    float acc[4][4];
    #pragma unroll
    for (int i = 0; i < 4; i++)
        #pragma unroll
        for (int j = 0; j < 4; j++) acc[i][j] = 0.f;

    int Ktot = 4 * F;
    for (int kt = 0; kt < Ktot; kt += 8) {
        int seg = kt / F;                    // whole 8-chunk lies in one segment
        int fk0 = kt - seg * F;
        const float* Ap = (seg == 0) ? A0 : (Zb + (size_t)(seg - 1) * SLICE);
        #pragma unroll
        for (int i = 0; i < 2; i++) {
            int e = tid + i * 256;
            int mm = e >> 3, kk = e & 7;
            As[kk][mm] = Ap[(size_t)(m0 + mm) * F + fk0 + kk];
        }
        #pragma unroll
        for (int i = 0; i < 2; i++) {
            int e = tid + i * 256;
            int kk = e >> 6, nn = e & 63;
            int col = n0 + nn;
            Ws[kk][nn] = (col < No) ? W[(size_t)(kt + kk) * No + col] : 0.f;
        }
        __syncthreads();
        #pragma unroll
        for (int kk = 0; kk < 8; kk++) {
            float4 a = *(const float4*)&As[kk][tr << 2];
            float4 b = *(const float4*)&Ws[kk][tc << 2];
            acc[0][0] += a.x * b.x; acc[0][1] += a.x * b.y; acc[0][2] += a.x * b.z; acc[0][3] += a.x * b.w;
            acc[1][0] += a.y * b.x; acc[1][1] += a.y * b.y; acc[1][2] += a.y * b.z; acc[1][3] += a.y * b.w;
            acc[2][0] += a.z * b.x; acc[2][1] += a.z * b.y; acc[2][2] += a.z * b.z; acc[2][3] += a.z * b.w;
            acc[3][0] += a.w * b.x; acc[3][1] += a.w * b.y; acc[3][2] += a.w * b.z; acc[3][3] += a.w * b.w;
        }
        __syncthreads();
    }
    #pragma unroll
    for (int i = 0; i < 4; i++) {
        int mr = m0 + (tr << 2) + i;
        #pragma unroll
        for (int j = 0; j < 4; j++) {
            int col = n0 + (tc << 2) + j;
            if (col < No) C[(size_t)mr * No + col] = acc[i][j];
        }
    }
}

__global__ void zero_stats_k(float* s, float* q) {
    s[threadIdx.x] = 0.f; q[threadIdx.x] = 0.f;
}

__global__ void bn_reduce_k(const float* __restrict__ Y, size_t total, int mask,
                            float* __restrict__ sums, float* __restrict__ sqs) {
    __shared__ float ss[256], qq[256];
    int tid = threadIdx.x;
    ss[tid] = 0.f; qq[tid] = 0.f;
    __syncthreads();
    for (size_t e = (size_t)blockIdx.x * blockDim.x + tid; e < total;
         e += (size_t)gridDim.x * blockDim.x) {
        float v = Y[e];
        int f = (int)(e & (size_t)mask);
        atomicAdd(&ss[f], v);
        atomicAdd(&qq[f], v * v);
    }
    __syncthreads();
    if (tid <= mask) { atomicAdd(&sums[tid], ss[tid]); atomicAdd(&sqs[tid], qq[tid]); }
}

__global__ void bn_apply_k(float* __restrict__ Y, const float* __restrict__ g,
                           const float* __restrict__ b, size_t total, int mask,
                           float invM, const float* __restrict__ sums,
                           const float* __restrict__ sqs) {
    size_t e = (size_t)blockIdx.x * blockDim.x + threadIdx.x;
    if (e >= total) return;
    int f = (int)(e & (size_t)mask);
    float mu = sums[f] * invM;
    float var = sqs[f] * invM - mu * mu;
    float v = (Y[e] - mu) * rsqrtf(var + 1e-5f) * g[f] + b[f];
    Y[e] = v > 0.f ? v : 0.f;
}

// 4:1 max pooling along n (nested groups of 4). In: (4*Nout, B, F) -> Out: (Nout, B, F)
__global__ void pool_k(const float* __restrict__ In, float* __restrict__ Out,
                       int Nout, int F) {
    int t = blockIdx.x * blockDim.x + threadIdx.x;
    int total = Nout * BG * F;
    if (t >= total) return;
    int f = t % F; int rb = t / F; int b = rb % BG; int n2 = rb / BG;
    size_t base = ((size_t)(n2 * 4) * BG + b) * F + f;
    size_t stride = (size_t)BG * F;
    float v = In[base];
    v = fmaxf(v, In[base + stride]);
    v = fmaxf(v, In[base + 2 * stride]);
    v = fmaxf(v, In[base + 3 * stride]);
    Out[t] = v;
}

// Out(n,b,0:Fu) = H(n/4,b,:) ; Out(n,b,Fu:Fu+Fs) = S(n,b,:)
__global__ void unpool_concat_k(const float* __restrict__ H, const float* __restrict__ S,
                                float* __restrict__ Out, int N, int Fu, int Fs) {
    int Fc = Fu + Fs;
    size_t total = (size_t)N * BG * Fc;
    size_t t = (size_t)blockIdx.x * blockDim.x + threadIdx.x;
    if (t >= total) return;
    int f = (int)(t % Fc);
    size_t rb = t / Fc;
    int b = (int)(rb % BG);
    int n = (int)(rb / BG);
    float v;
    if (f < Fu) v = H[(((size_t)(n >> 2)) * BG + b) * Fu + f];
    else        v = S[(((size_t)n) * BG + b) * Fs + (f - Fu)];
    Out[t] = v;
}

// Final layer: Fout = 1. One warp per row, F = 32.
__global__ void out_layer_k(const float* __restrict__ A0, const float* __restrict__ Zb,
                            const float* __restrict__ W, float* __restrict__ C, int M) {
    int gw = (int)((blockIdx.x * blockDim.x + threadIdx.x) >> 5);
    int lane = threadIdx.x & 31;
    if (gw >= M) return;
    size_t r = (size_t)gw * 32 + lane;
    float acc = A0[r] * W[lane]
              + Zb[r] * W[32 + lane]
              + Zb[SLICE + r] * W[64 + lane]
              + Zb[2 * SLICE + r] * W[96 + lane];
    #pragma unroll
    for (int o = 16; o; o >>= 1) acc += __shfl_down_sync(0xffffffffu, acc, o);
    if (lane == 0) C[gw] = acc;
}

// Y layout row = n*256 + bg  ->  out (4,1,8,8,768)
__global__ void reshape_out_k(const float* __restrict__ Y, float* __restrict__ out) {
    int t = blockIdx.x * blockDim.x + threadIdx.x;  // 196,608
    int n = t % 768;
    int r = t / 768;
    int hw = r & 63;
    int b0 = r >> 6;
    out[t] = Y[(size_t)n * BG + (size_t)b0 * 64 + hw];
}

// ---------------- host orchestration ----------------

extern "C" void kernel_launch(void* const* d_in, const int* in_sizes, int n_in,
                              void* d_out, int out_size) {
    const float* x = (const float*)d_in[0];
    const float* Ls[4] = {(const float*)d_in[1], (const float*)d_in[2],
                          (const float*)d_in[3], (const float*)d_in[4]};
    const int Nlv[4] = {768, 192, 48, 12};

    float *A_, *B_, *Z_, *S3, *S2, *S1, *sum_, *sq_, *cval;
    int *cidx, *cnnz;
    cudaGetSymbolAddress((void**)&A_,  g_A);
    cudaGetSymbolAddress((void**)&B_,  g_B);
    cudaGetSymbolAddress((void**)&Z_,  g_Z);
    cudaGetSymbolAddress((void**)&S3,  g_S3);
    cudaGetSymbolAddress((void**)&S2,  g_S2);
    cudaGetSymbolAddress((void**)&S1,  g_S1);
    cudaGetSymbolAddress((void**)&sum_, g_sum);
    cudaGetSymbolAddress((void**)&sq_,  g_sq);
    cudaGetSymbolAddress((void**)&cidx, g_cidx);
    cudaGetSymbolAddress((void**)&cval, g_cval);
    cudaGetSymbolAddress((void**)&cnnz, g_cnnz);

    // sparse structure, once per call
    for (int l = 0; l < 4; l++)
        build_csr_k<<<(Nlv[l] + 127) / 128, 128>>>(
            Ls[l], Nlv[l], cidx + l * 768 * MAXNNZ, cval + l * 768 * MAXNNZ, cnnz + l * 768);

    transpose_in_k<<<6144, 256>>>(x, A_);

    auto spmm3 = [&](int lvl, int N, int F, const float* in) {
        int cols4 = BG * F / 4;
        dim3 gs(cols4 / 256, N);
        const int* ci = cidx + lvl * 768 * MAXNNZ;
        const float* cv = cval + lvl * 768 * MAXNNZ;
        const int* cn = cnnz + lvl * 768;
        // x1 = L x0
        spmm_k<<<gs, 256>>>(ci, cv, cn, cols4, (const float4*)in, (float4*)Z_, 1.f, nullptr);
        // x2 = 2 L x1 - x0
        spmm_k<<<gs, 256>>>(ci, cv, cn, cols4, (const float4*)Z_, (float4*)(Z_ + SLICE), 2.f,
                            (const float4*)in);
        // x3 = 2 L x2 - x1
        spmm_k<<<gs, 256>>>(ci, cv, cn, cols4, (const float4*)(Z_ + SLICE),
                            (float4*)(Z_ + 2 * SLICE), 2.f, (const float4*)Z_);
    };

    auto cheb = [&](int lvl, int N, int F, int Fo, const float* w, const float* gg,
                    const float* bb, const float* in, float* out) {
        spmm3(lvl, N, F, in);
        int M = N * BG;
        dim3 g2(M / 64, (Fo + 63) / 64);
        stageb_k<<<g2, 256>>>(in, Z_, w, out, M, F, Fo);
        size_t tot = (size_t)M * Fo;
        zero_stats_k<<<1, 256>>>(sum_, sq_);
        bn_reduce_k<<<512, 256>>>(out, tot, Fo - 1, sum_, sq_);
        bn_apply_k<<<(unsigned)((tot + 255) / 256), 256>>>(out, gg, bb, tot, Fo - 1,
                                                           1.0f / (float)M, sum_, sq_);
    };

    const float* w_e3a = (const float*)d_in[5];
    const float* g_e3a_ = (const float*)d_in[6];  const float* b_e3a_ = (const float*)d_in[7];
    const float* w_e3b = (const float*)d_in[8];
    const float* g_e3b_ = (const float*)d_in[9];  const float* b_e3b_ = (const float*)d_in[10];
    const float* w_e2 = (const float*)d_in[11];
    const float* g_e2_ = (const float*)d_in[12];  const float* b_e2_ = (const float*)d_in[13];
    const float* w_e1 = (const float*)d_in[14];
    const float* g_e1_ = (const float*)d_in[15];  const float* b_e1_ = (const float*)d_in[16];
    const float* w_e0 = (const float*)d_in[17];
    const float* g_e0_ = (const float*)d_in[18];  const float* b_e0_ = (const float*)d_in[19];
    const float* w_d1 = (const float*)d_in[20];
    const float* g_d1_ = (const float*)d_in[21];  const float* b_d1_ = (const float*)d_in[22];
    const float* w_d2 = (const float*)d_in[23];
    const float* g_d2_ = (const float*)d_in[24];  const float* b_d2_ = (const float*)d_in[25];
    const float* w_d3 = (const float*)d_in[26];
    const float* g_d3_ = (const float*)d_in[27];  const float* b_d3_ = (const float*)d_in[28];
    const float* w_out = (const float*)d_in[29];

    // encoder
    cheb(0, 768,   8,  32, w_e3a, g_e3a_, b_e3a_, A_, B_);
    cheb(0, 768,  32,  64, w_e3b, g_e3b_, b_e3b_, B_, S3);
    pool_k<<<(192 * BG * 64 + 255) / 256, 256>>>(S3, A_, 192, 64);
    cheb(1, 192,  64, 128, w_e2, g_e2_, b_e2_, A_, S2);
    pool_k<<<(48 * BG * 128 + 255) / 256, 256>>>(S2, A_, 48, 128);
    cheb(2, 48,  128, 256, w_e1, g_e1_, b_e1_, A_, S1);
    pool_k<<<(12 * BG * 256 + 255) / 256, 256>>>(S1, A_, 12, 256);
    cheb(3, 12,  256, 256, w_e0, g_e0_, b_e0_, A_, B_);
    // decoder
    unpool_concat_k<<<(48 * BG * 512 + 255) / 256, 256>>>(B_, S1, A_, 48, 256, 256);
    cheb(2, 48,  512, 128, w_d1, g_d1_, b_d1_, A_, B_);
    unpool_concat_k<<<(192 * BG * 256 + 255) / 256, 256>>>(B_, S2, A_, 192, 128, 128);
    cheb(1, 192, 256,  64, w_d2, g_d2_, b_d2_, A_, B_);
    unpool_concat_k<<<(768 * BG * 128 + 255) / 256, 256>>>(B_, S3, A_, 768, 64, 64);
    cheb(0, 768, 128,  32, w_d3, g_d3_, b_d3_, A_, B_);
    // output cheb layer (Fout = 1, no BN)
    spmm3(0, 768, 32, B_);
    out_layer_k<<<(196608 * 32 + 255) / 256, 256>>>(B_, Z_, w_out, A_, 196608);
    reshape_out_k<<<196608 / 256, 256>>>(A_, (float*)d_out);
}

// round 5
// speedup vs baseline: 1.1678x; 1.1678x over previous
#include <cuda_runtime.h>
#include <cstdint>
#include <cstddef>

#define MAXNNZ 40
#define BG 256
#define SLICE 25165824UL   // 768*256*128 floats (largest N*B*F slab)

// ---------------- static scratch (no allocation allowed) ----------------
__device__ float g_A[SLICE];                 // ping buffer (N,B,F)
__device__ float g_B[SLICE];                 // pong buffer
__device__ float g_Z[3*SLICE];               // Chebyshev / Horner temporaries
__device__ float g_S3[768*256*64];           // skip s3
__device__ float g_S2[192*256*128];          // skip s2
__device__ float g_S1[48*256*256];           // skip s1
__device__ float g_Wc[4*512*128];            // combined Horner weights
__device__ int   g_cidx[4*768*MAXNNZ];       // ELL col indices per level
__device__ float g_cval[4*768*MAXNNZ];       // ELL values
__device__ int   g_cnnz[4*768];              // per-row nnz
__device__ float g_sum[256];                 // BN channel sums
__device__ float g_sq[256];                  // BN channel sum-of-squares

// ---------------- kernels ----------------

// Extract ELL sparse structure for all 4 levels in one launch.
__global__ void build_all_k(const float* __restrict__ L3, const float* __restrict__ L2,
                            const float* __restrict__ L1, const float* __restrict__ L0,
                            int* __restrict__ idx, float* __restrict__ val,
                            int* __restrict__ nnz) {
    int t = blockIdx.x * blockDim.x + threadIdx.x;
    if (t >= 1020) return;
    int lvl, n, N;
    const float* L;
    if (t < 768)       { lvl = 0; n = t;        N = 768; L = L3; }
    else if (t < 960)  { lvl = 1; n = t - 768;  N = 192; L = L2; }
    else if (t < 1008) { lvl = 2; n = t - 960;  N = 48;  L = L1; }
    else               { lvl = 3; n = t - 1008; N = 12;  L = L0; }
    int base = (lvl * 768 + n) * MAXNNZ;
    int c = 0;
    for (int m = 0; m < N; m++) {
        float v = L[n * N + m];
        if (v != 0.0f && c < MAXNNZ) {
            idx[base + c] = m;
            val[base + c] = v;
            c++;
        }
    }
    nnz[lvl * 768 + n] = c;
}

// x (4,8,8,8,768) -> A layout (n, bg, c) with bg = b0*64 + hw
__global__ void transpose_in_k(const float* __restrict__ x, float* __restrict__ A) {
    int t = blockIdx.x * blockDim.x + threadIdx.x;  // 1,572,864 total
    int n = t % 768;
    int r = t / 768;
    int hw = r & 63; r >>= 6;
    int c = r & 7;  int b0 = r >> 3;
    A[((size_t)n * BG + (size_t)b0 * 64 + hw) * 8 + c] = x[t];
}

// Z[row,:] = alpha * sum_j L[row,col_j] * X[col_j,:]  (- S[row,:] if S)
__global__ void spmm_k(const int* __restrict__ idx, const float* __restrict__ val,
                       const int* __restrict__ nnz, int cols4,
                       const float4* __restrict__ X, float4* __restrict__ Z,
                       float alpha, const float4* __restrict__ S) {
    int row = blockIdx.y;
    int c = blockIdx.x * blockDim.x + threadIdx.x;
    __shared__ int   si[MAXNNZ];
    __shared__ float sv[MAXNNZ];
    __shared__ int   sn;
    int tid = threadIdx.x;
    if (tid < MAXNNZ) { si[tid] = idx[row * MAXNNZ + tid]; sv[tid] = val[row * MAXNNZ + tid]; }
    if (tid == 0) sn = nnz[row];
    __syncthreads();
    float4 acc = make_float4(0.f, 0.f, 0.f, 0.f);
    int nn = sn;
    #pragma unroll 4
    for (int j = 0; j < nn; j++) {
        float v = sv[j];
        float4 xv = __ldg(&X[(size_t)si[j] * cols4 + c]);
        acc.x += v * xv.x; acc.y += v * xv.y; acc.z += v * xv.z; acc.w += v * xv.w;
    }
    size_t o = (size_t)row * cols4 + c;
    float4 out;
    if (S) {
        float4 s = S[o];
        out = make_float4(alpha * acc.x - s.x, alpha * acc.y - s.y,
                          alpha * acc.z - s.z, alpha * acc.w - s.w);
    } else {
        out = make_float4(alpha * acc.x, alpha * acc.y, alpha * acc.z, alpha * acc.w);
    }
    Z[o] = out;
}

// Combined Horner weights: step0=4*w3, step1=2*w2, step2=w1-3*w3, step3=w0-w2
__global__ void wcomb_k(const float* __restrict__ w, float* __restrict__ wc, int FFo) {
    int i = blockIdx.x * blockDim.x + threadIdx.x;
    if (i >= FFo) return;
    float w0 = w[i], w1 = w[FFo + i], w2 = w[2 * FFo + i], w3 = w[3 * FFo + i];
    wc[i]           = 4.f * w3;
    wc[FFo + i]     = 2.f * w2;
    wc[2 * FFo + i] = w1 - 3.f * w3;
    wc[3 * FFo + i] = w0 - w2;
}

// C(M x No) = [segmented A](M x nseg*F) @ W(nseg*F x No) [+ Cin] [+ BN stats]
// Segments: seg0 = A0, seg k>0 = Zb + (k-1)*SLICE. 128 x TN tile, 8x8 per thread.
template<int TN>
__global__ __launch_bounds__(2 * TN) void gemm_k(
        const float* __restrict__ A0, const float* __restrict__ Zb,
        const float* __restrict__ W, const float* __restrict__ Cin,
        float* __restrict__ C, int F, int nseg, int No,
        float* __restrict__ sums, float* __restrict__ sqs) {
    __shared__ float As[8][132];
    __shared__ float Ws[8][TN + 4];
    __shared__ float csum[TN], csq[TN];
    const int NT = 2 * TN;
    int tid = threadIdx.x;
    int m0 = blockIdx.x * 128, n0 = blockIdx.y * TN;
    int tx = tid % (TN / 8), ty = tid / (TN / 8);
    float acc[8][8];
    #pragma unroll
    for (int i = 0; i < 8; i++)
        #pragma unroll
        for (int j = 0; j < 8; j++) acc[i][j] = 0.f;

    int Ktot = nseg * F;
    for (int kt = 0; kt < Ktot; kt += 8) {
        int seg = kt / F;                  // whole 8-chunk lies in one segment (F%8==0)
        int fk0 = kt - seg * F;
        const float* Ap = (seg == 0) ? A0 : (Zb + (size_t)(seg - 1) * SLICE);
        #pragma unroll
        for (int i = 0; i < 1024 / NT; i++) {
            int e = tid + i * NT;
            int mm = e >> 3, kk = e & 7;
            As[kk][mm] = Ap[(size_t)(m0 + mm) * F + fk0 + kk];
        }
        #pragma unroll
        for (int i = 0; i < 4; i++) {
            int e = tid + i * NT;
            int kk = e / TN, nn = e % TN;
            int col = n0 + nn;
            Ws[kk][nn] = (col < No) ? W[(size_t)(kt + kk) * No + col] : 0.f;
        }
        __syncthreads();
        #pragma unroll
        for (int kk = 0; kk < 8; kk++) {
            float4 a0v = *(const float4*)&As[kk][ty * 8];
            float4 a1v = *(const float4*)&As[kk][ty * 8 + 4];
            float4 b0v = *(const float4*)&Ws[kk][tx * 8];
            float4 b1v = *(const float4*)&Ws[kk][tx * 8 + 4];
            float av[8] = {a0v.x, a0v.y, a0v.z, a0v.w, a1v.x, a1v.y, a1v.z, a1v.w};
            float bv[8] = {b0v.x, b0v.y, b0v.z, b0v.w, b1v.x, b1v.y, b1v.z, b1v.w};
            #pragma unroll
            for (int i = 0; i < 8; i++)
                #pragma unroll
                for (int j = 0; j < 8; j++)
                    acc[i][j] += av[i] * bv[j];
        }
        __syncthreads();
    }

    float cp[8], cq[8];
    #pragma unroll
    for (int j = 0; j < 8; j++) { cp[j] = 0.f; cq[j] = 0.f; }
    #pragma unroll
    for (int i = 0; i < 8; i++) {
        size_t r = (size_t)(m0 + ty * 8 + i);
        #pragma unroll
        for (int j = 0; j < 8; j++) {
            int col = n0 + tx * 8 + j;
            if (col < No) {
                size_t o = r * No + col;
                float v = acc[i][j];
                if (Cin) v += Cin[o];
                C[o] = v;
                cp[j] += v; cq[j] += v * v;
            }
        }
    }
    if (sums) {
        if (tid < TN) { csum[tid] = 0.f; csq[tid] = 0.f; }
        __syncthreads();
        #pragma unroll
        for (int j = 0; j < 8; j++) {
            atomicAdd(&csum[tx * 8 + j], cp[j]);
            atomicAdd(&csq[tx * 8 + j], cq[j]);
        }
        __syncthreads();
        if (tid < TN && n0 + tid < No) {
            atomicAdd(&sums[n0 + tid], csum[tid]);
            atomicAdd(&sqs[n0 + tid], csq[tid]);
        }
    }
}

__global__ void zero_stats_k(float* s, float* q) {
    s[threadIdx.x] = 0.f; q[threadIdx.x] = 0.f;
}

__global__ void bn_apply_k(float* __restrict__ Y, const float* __restrict__ g,
                           const float* __restrict__ b, size_t total, int mask,
                           float invM, const float* __restrict__ sums,
                           const float* __restrict__ sqs) {
    size_t e = (size_t)blockIdx.x * blockDim.x + threadIdx.x;
    if (e >= total) return;
    int f = (int)(e & (size_t)mask);
    float mu = sums[f] * invM;
    float var = sqs[f] * invM - mu * mu;
    float v = (Y[e] - mu) * rsqrtf(var + 1e-5f) * g[f] + b[f];
    Y[e] = v > 0.f ? v : 0.f;
}

// 4:1 max pooling along n. In: (4*Nout, B, F) -> Out: (Nout, B, F)
__global__ void pool_k(const float* __restrict__ In, float* __restrict__ Out,
                       int Nout, int F) {
    int t = blockIdx.x * blockDim.x + threadIdx.x;
    int total = Nout * BG * F;
    if (t >= total) return;
    int f = t % F; int rb = t / F; int b = rb % BG; int n2 = rb / BG;
    size_t base = ((size_t)(n2 * 4) * BG + b) * F + f;
    size_t stride = (size_t)BG * F;
    float v = In[base];
    v = fmaxf(v, In[base + stride]);
    v = fmaxf(v, In[base + 2 * stride]);
    v = fmaxf(v, In[base + 3 * stride]);
    Out[t] = v;
}

// Out(n,b,0:Fu) = H(n/4,b,:) ; Out(n,b,Fu:Fu+Fs) = S(n,b,:)
__global__ void unpool_concat_k(const float* __restrict__ H, const float* __restrict__ S,
                                float* __restrict__ Out, int N, int Fu, int Fs) {
    int Fc = Fu + Fs;
    size_t total = (size_t)N * BG * Fc;
    size_t t = (size_t)blockIdx.x * blockDim.x + threadIdx.x;
    if (t >= total) return;
    int f = (int)(t % Fc);
    size_t rb = t / Fc;
    int b = (int)(rb % BG);
    int n = (int)(rb / BG);
    float v;
    if (f < Fu) v = H[(((size_t)(n >> 2)) * BG + b) * Fu + f];
    else        v = S[(((size_t)n) * BG + b) * Fs + (f - Fu)];
    Out[t] = v;
}

// C[r] = dot(X[r, 0:32], w) (+ Cin[r]). One warp per row.
__global__ void proj1_k(const float* __restrict__ X, const float* __restrict__ w,
                        const float* __restrict__ Cin, float* __restrict__ C, int M) {
    int gw = (int)((blockIdx.x * blockDim.x + threadIdx.x) >> 5);
    int lane = threadIdx.x & 31;
    if (gw >= M) return;
    float acc = X[(size_t)gw * 32 + lane] * w[lane];
    #pragma unroll
    for (int o = 16; o; o >>= 1) acc += __shfl_down_sync(0xffffffffu, acc, o);
    if (lane == 0) C[gw] = acc + (Cin ? Cin[gw] : 0.f);
}

// Y layout row = n*256 + bg  ->  out (4,1,8,8,768)
__global__ void reshape_out_k(const float* __restrict__ Y, float* __restrict__ out) {
    int t = blockIdx.x * blockDim.x + threadIdx.x;  // 196,608
    int n = t % 768;
    int r = t / 768;
    int hw = r & 63;
    int b0 = r >> 6;
    out[t] = Y[(size_t)n * BG + (size_t)b0 * 64 + hw];
}

// ---------------- host side ----------------

static void run_gemm(const float* A0, const float* Zb, const float* W, const float* Cin,
                     float* C, int M, int F, int nseg, int No, float* sums, float* sqs) {
    if (No >= 128) {
        dim3 g(M / 128, (No + 127) / 128);
        gemm_k<128><<<g, 256>>>(A0, Zb, W, Cin, C, F, nseg, No, sums, sqs);
    } else if (No >= 64) {
        dim3 g(M / 128, 1);
        gemm_k<64><<<g, 128>>>(A0, Zb, W, Cin, C, F, nseg, No, sums, sqs);
    } else {
        dim3 g(M / 128, 1);
        gemm_k<32><<<g, 64>>>(A0, Zb, W, Cin, C, F, nseg, No, sums, sqs);
    }
}

extern "C" void kernel_launch(void* const* d_in, const int* in_sizes, int n_in,
                              void* d_out, int out_size) {
    const float* x = (const float*)d_in[0];

    float *A_, *B_, *Z_, *S3, *S2, *S1, *Wc, *sum_, *sq_, *cval;
    int *cidx, *cnnz;
    cudaGetSymbolAddress((void**)&A_,  g_A);
    cudaGetSymbolAddress((void**)&B_,  g_B);
    cudaGetSymbolAddress((void**)&Z_,  g_Z);
    cudaGetSymbolAddress((void**)&S3,  g_S3);
    cudaGetSymbolAddress((void**)&S2,  g_S2);
    cudaGetSymbolAddress((void**)&S1,  g_S1);
    cudaGetSymbolAddress((void**)&Wc,  g_Wc);
    cudaGetSymbolAddress((void**)&sum_, g_sum);
    cudaGetSymbolAddress((void**)&sq_,  g_sq);
    cudaGetSymbolAddress((void**)&cidx, g_cidx);
    cudaGetSymbolAddress((void**)&cval, g_cval);
    cudaGetSymbolAddress((void**)&cnnz, g_cnnz);

    build_all_k<<<8, 128>>>((const float*)d_in[1], (const float*)d_in[2],
                            (const float*)d_in[3], (const float*)d_in[4],
                            cidx, cval, cnnz);
    transpose_in_k<<<6144, 256>>>(x, A_);

    // single SpMM: out = L * in   (slab cols = BG*F floats)
    auto spmm1 = [&](int lvl, int N, int F, const float* in, float* out,
                     float alpha, const float* S) {
        int cols4 = BG * F / 4;
        int thr = cols4 < 256 ? cols4 : 256;
        dim3 gs(cols4 / thr, N);
        spmm_k<<<gs, thr>>>(cidx + lvl * 768 * MAXNNZ, cval + lvl * 768 * MAXNNZ,
                            cnnz + lvl * 768, cols4, (const float4*)in, (float4*)out,
                            alpha, (const float4*)S);
    };

    // encoder-order Chebyshev recurrence: x1,x2,x3 into Z slices
    auto spmm3 = [&](int lvl, int N, int F, const float* in) {
        spmm1(lvl, N, F, in, Z_, 1.f, nullptr);
        spmm1(lvl, N, F, Z_, Z_ + SLICE, 2.f, in);
        spmm1(lvl, N, F, Z_ + SLICE, Z_ + 2 * SLICE, 2.f, Z_);
    };

    // encoder layer: spmm in Fin space, 4-segment GEMM with fused BN stats
    auto enc = [&](int lvl, int N, int F, int Fo, const float* w, const float* gg,
                   const float* bb, const float* in, float* out) {
        spmm3(lvl, N, F, in);
        int M = N * BG;
        zero_stats_k<<<1, 256>>>(sum_, sq_);
        run_gemm(in, Z_, w, nullptr, out, M, F, 4, Fo, sum_, sq_);
        size_t tot = (size_t)M * Fo;
        bn_apply_k<<<(unsigned)((tot + 255) / 256), 256>>>(out, gg, bb, tot, Fo - 1,
                                                           1.0f / (float)M, sum_, sq_);
    };

    // decoder layer (Fo < F): Horner form, spmm in Fout space
    auto deco = [&](int lvl, int N, int F, int Fo, const float* w, const float* gg,
                    const float* bb, const float* in, float* out) {
        int FFo = F * Fo;
        wcomb_k<<<(FFo + 255) / 256, 256>>>(w, Wc, FFo);
        int M = N * BG;
        float* Z0 = Z_; float* Z1 = Z_ + SLICE; float* Z2 = Z_ + 2 * SLICE;
        run_gemm(in, nullptr, Wc,           nullptr, Z0, M, F, 1, Fo, nullptr, nullptr);
        spmm1(lvl, N, Fo, Z0, Z1, 1.f, nullptr);
        run_gemm(in, nullptr, Wc + FFo,     Z1,      Z1, M, F, 1, Fo, nullptr, nullptr);
        spmm1(lvl, N, Fo, Z1, Z2, 1.f, nullptr);
        run_gemm(in, nullptr, Wc + 2 * FFo, Z2,      Z2, M, F, 1, Fo, nullptr, nullptr);
        spmm1(lvl, N, Fo, Z2, out, 1.f, nullptr);
        zero_stats_k<<<1, 256>>>(sum_, sq_);
        run_gemm(in, nullptr, Wc + 3 * FFo, out,     out, M, F, 1, Fo, sum_, sq_);
        size_t tot = (size_t)M * Fo;
        bn_apply_k<<<(unsigned)((tot + 255) / 256), 256>>>(out, gg, bb, tot, Fo - 1,
                                                           1.0f / (float)M, sum_, sq_);
    };

    const float* w_e3a = (const float*)d_in[5];
    const float* g_e3a_ = (const float*)d_in[6];  const float* b_e3a_ = (const float*)d_in[7];
    const float* w_e3b = (const float*)d_in[8];
    const float* g_e3b_ = (const float*)d_in[9];  const float* b_e3b_ = (const float*)d_in[10];
    const float* w_e2 = (const float*)d_in[11];
    const float* g_e2_ = (const float*)d_in[12];  const float* b_e2_ = (const float*)d_in[13];
    const float* w_e1 = (const float*)d_in[14];
    const float* g_e1_ = (const float*)d_in[15];  const float* b_e1_ = (const float*)d_in[16];
    const float* w_e0 = (const float*)d_in[17];
    const float* g_e0_ = (const float*)d_in[18];  const float* b_e0_ = (const float*)d_in[19];
    const float* w_d1 = (const float*)d_in[20];
    const float* g_d1_ = (const float*)d_in[21];  const float* b_d1_ = (const float*)d_in[22];
    const float* w_d2 = (const float*)d_in[23];
    const float* g_d2_ = (const float*)d_in[24];  const float* b_d2_ = (const float*)d_in[25];
    const float* w_d3 = (const float*)d_in[26];
    const float* g_d3_ = (const float*)d_in[27];  const float* b_d3_ = (const float*)d_in[28];
    const float* w_out = (const float*)d_in[29];

    // encoder
    enc(0, 768,   8,  32, w_e3a, g_e3a_, b_e3a_, A_, B_);
    enc(0, 768,  32,  64, w_e3b, g_e3b_, b_e3b_, B_, S3);
    pool_k<<<(192 * BG * 64 + 255) / 256, 256>>>(S3, A_, 192, 64);
    enc(1, 192,  64, 128, w_e2, g_e2_, b_e2_, A_, S2);
    pool_k<<<(48 * BG * 128 + 255) / 256, 256>>>(S2, A_, 48, 128);
    enc(2, 48,  128, 256, w_e1, g_e1_, b_e1_, A_, S1);
    pool_k<<<(12 * BG * 256 + 255) / 256, 256>>>(S1, A_, 12, 256);
    enc(3, 12,  256, 256, w_e0, g_e0_, b_e0_, A_, B_);
    // decoder (Horner order)
    unpool_concat_k<<<(48 * BG * 512 + 255) / 256, 256>>>(B_, S1, A_, 48, 256, 256);
    deco(2, 48,  512, 128, w_d1, g_d1_, b_d1_, A_, B_);
    unpool_concat_k<<<(192 * BG * 256 + 255) / 256, 256>>>(B_, S2, A_, 192, 128, 128);
    deco(1, 192, 256,  64, w_d2, g_d2_, b_d2_, A_, B_);
    unpool_concat_k<<<(768 * BG * 128 + 255) / 256, 256>>>(B_, S3, A_, 768, 64, 64);
    deco(0, 768, 128,  32, w_d3, g_d3_, b_d3_, A_, B_);

    // out layer (32 -> 1), Horner in 1-channel space: essentially free spmms
    {
        int M = 196608;
        wcomb_k<<<(32 * 1 + 255) / 256, 256>>>(w_out, Wc, 32);
        float* Z0 = Z_; float* Z1 = Z_ + SLICE; float* Z2 = Z_ + 2 * SLICE;
        int pb = (M * 32 + 255) / 256;
        proj1_k<<<pb, 256>>>(B_, Wc,      nullptr, Z0, M);
        spmm1(0, 768, 1, Z0, Z1, 1.f, nullptr);
        proj1_k<<<pb, 256>>>(B_, Wc + 32, Z1,      Z1, M);
        spmm1(0, 768, 1, Z1, Z2, 1.f, nullptr);
        proj1_k<<<pb, 256>>>(B_, Wc + 64, Z2,      Z2, M);
        spmm1(0, 768, 1, Z2, A_, 1.f, nullptr);
        proj1_k<<<pb, 256>>>(B_, Wc + 96, A_,      A_, M);
    }
    reshape_out_k<<<196608 / 256, 256>>>(A_, (float*)d_out);
}

// round 6
// speedup vs baseline: 1.6148x; 1.3828x over previous
#include <cuda_runtime.h>
#include <cuda_bf16.h>
#include <cstdint>
#include <cstddef>

#define MAXNNZ 40
#define BG 256
#define SLICE 25165824UL   // 768*256*128 floats (largest N*B*F slab)

// ---------------- static scratch (no allocation allowed) ----------------
__device__ float g_A[SLICE];                 // ping buffer (N,B,F)
__device__ float g_B[SLICE];                 // pong buffer
__device__ float g_Z[3*SLICE];               // Chebyshev / Horner temporaries
__device__ float g_S3[768*256*64];           // skip s3
__device__ float g_S2[192*256*128];          // skip s2
__device__ float g_S1[48*256*256];           // skip s1
__device__ float g_Wc[4*512*128];            // combined Horner weights
__device__ int   g_cidx[4*768*MAXNNZ];       // ELL col indices per level
__device__ float g_cval[4*768*MAXNNZ];       // ELL values
__device__ int   g_cnnz[4*768];              // per-row nnz
__device__ float g_sum[256];                 // BN channel sums
__device__ float g_sq[256];                  // BN channel sum-of-squares

// ---------------- kernels ----------------

// Extract ELL sparse structure for all 4 levels in one launch.
__global__ void build_all_k(const float* __restrict__ L3, const float* __restrict__ L2,
                            const float* __restrict__ L1, const float* __restrict__ L0,
                            int* __restrict__ idx, float* __restrict__ val,
                            int* __restrict__ nnz) {
    int t = blockIdx.x * blockDim.x + threadIdx.x;
    if (t >= 1020) return;
    int lvl, n, N;
    const float* L;
    if (t < 768)       { lvl = 0; n = t;        N = 768; L = L3; }
    else if (t < 960)  { lvl = 1; n = t - 768;  N = 192; L = L2; }
    else if (t < 1008) { lvl = 2; n = t - 960;  N = 48;  L = L1; }
    else               { lvl = 3; n = t - 1008; N = 12;  L = L0; }
    int base = (lvl * 768 + n) * MAXNNZ;
    int c = 0;
    for (int m = 0; m < N; m++) {
        float v = L[n * N + m];
        if (v != 0.0f && c < MAXNNZ) {
            idx[base + c] = m;
            val[base + c] = v;
            c++;
        }
    }
    nnz[lvl * 768 + n] = c;
}

// x (4,8,8,8,768) -> A layout (n, bg, c) with bg = b0*64 + hw
__global__ void transpose_in_k(const float* __restrict__ x, float* __restrict__ A) {
    int t = blockIdx.x * blockDim.x + threadIdx.x;  // 1,572,864 total
    int n = t % 768;
    int r = t / 768;
    int hw = r & 63; r >>= 6;
    int c = r & 7;  int b0 = r >> 3;
    A[((size_t)n * BG + (size_t)b0 * 64 + hw) * 8 + c] = x[t];
}

// Z[row,:] = alpha * sum_j L[row,col_j] * X[col_j,:]  (- S[row,:] if S)
__global__ void spmm_k(const int* __restrict__ idx, const float* __restrict__ val,
                       const int* __restrict__ nnz, int cols4,
                       const float4* __restrict__ X, float4* __restrict__ Z,
                       float alpha, const float4* __restrict__ S) {
    int row = blockIdx.y;
    int c = blockIdx.x * blockDim.x + threadIdx.x;
    __shared__ int   si[MAXNNZ];
    __shared__ float sv[MAXNNZ];
    __shared__ int   sn;
    int tid = threadIdx.x;
    if (tid < MAXNNZ) { si[tid] = idx[row * MAXNNZ + tid]; sv[tid] = val[row * MAXNNZ + tid]; }
    if (tid == 0) sn = nnz[row];
    __syncthreads();
    float4 acc = make_float4(0.f, 0.f, 0.f, 0.f);
    int nn = sn;
    #pragma unroll 4
    for (int j = 0; j < nn; j++) {
        float v = sv[j];
        float4 xv = __ldg(&X[(size_t)si[j] * cols4 + c]);
        acc.x += v * xv.x; acc.y += v * xv.y; acc.z += v * xv.z; acc.w += v * xv.w;
    }
    size_t o = (size_t)row * cols4 + c;
    float4 out;
    if (S) {
        float4 s = S[o];
        out = make_float4(alpha * acc.x - s.x, alpha * acc.y - s.y,
                          alpha * acc.z - s.z, alpha * acc.w - s.w);
    } else {
        out = make_float4(alpha * acc.x, alpha * acc.y, alpha * acc.z, alpha * acc.w);
    }
    Z[o] = out;
}

// Combined Horner weights: step0=4*w3, step1=2*w2, step2=w1-3*w3, step3=w0-w2
__global__ void wcomb_k(const float* __restrict__ w, float* __restrict__ wc, int FFo) {
    int i = blockIdx.x * blockDim.x + threadIdx.x;
    if (i >= FFo) return;
    float w0 = w[i], w1 = w[FFo + i], w2 = w[2 * FFo + i], w3 = w[3 * FFo + i];
    wc[i]           = 4.f * w3;
    wc[FFo + i]     = 2.f * w2;
    wc[2 * FFo + i] = w1 - 3.f * w3;
    wc[3 * FFo + i] = w0 - w2;
}

// ---------------- fp32 fallback GEMM (small-F layers) ----------------
template<int TN>
__global__ __launch_bounds__(2 * TN) void gemm_k(
        const float* __restrict__ A0, const float* __restrict__ Zb,
        const float* __restrict__ W, const float* __restrict__ Cin,
        float* __restrict__ C, int F, int nseg, int No,
        float* __restrict__ sums, float* __restrict__ sqs) {
    __shared__ float As[8][132];
    __shared__ float Ws[8][TN + 4];
    __shared__ float csum[TN], csq[TN];
    const int NT = 2 * TN;
    int tid = threadIdx.x;
    int m0 = blockIdx.x * 128, n0 = blockIdx.y * TN;
    int tx = tid % (TN / 8), ty = tid / (TN / 8);
    float acc[8][8];
    #pragma unroll
    for (int i = 0; i < 8; i++)
        #pragma unroll
        for (int j = 0; j < 8; j++) acc[i][j] = 0.f;

    int Ktot = nseg * F;
    for (int kt = 0; kt < Ktot; kt += 8) {
        int seg = kt / F;
        int fk0 = kt - seg * F;
        const float* Ap = (seg == 0) ? A0 : (Zb + (size_t)(seg - 1) * SLICE);
        #pragma unroll
        for (int i = 0; i < 1024 / NT; i++) {
            int e = tid + i * NT;
            int mm = e >> 3, kk = e & 7;
            As[kk][mm] = Ap[(size_t)(m0 + mm) * F + fk0 + kk];
        }
        #pragma unroll
        for (int i = 0; i < 4; i++) {
            int e = tid + i * NT;
            int kk = e / TN, nn = e % TN;
            int col = n0 + nn;
            Ws[kk][nn] = (col < No) ? W[(size_t)(kt + kk) * No + col] : 0.f;
        }
        __syncthreads();
        #pragma unroll
        for (int kk = 0; kk < 8; kk++) {
            float4 a0v = *(const float4*)&As[kk][ty * 8];
            float4 a1v = *(const float4*)&As[kk][ty * 8 + 4];
            float4 b0v = *(const float4*)&Ws[kk][tx * 8];
            float4 b1v = *(const float4*)&Ws[kk][tx * 8 + 4];
            float av[8] = {a0v.x, a0v.y, a0v.z, a0v.w, a1v.x, a1v.y, a1v.z, a1v.w};
            float bv[8] = {b0v.x, b0v.y, b0v.z, b0v.w, b1v.x, b1v.y, b1v.z, b1v.w};
            #pragma unroll
            for (int i = 0; i < 8; i++)
                #pragma unroll
                for (int j = 0; j < 8; j++)
                    acc[i][j] += av[i] * bv[j];
        }
        __syncthreads();
    }

    float cp[8], cq[8];
    #pragma unroll
    for (int j = 0; j < 8; j++) { cp[j] = 0.f; cq[j] = 0.f; }
    #pragma unroll
    for (int i = 0; i < 8; i++) {
        size_t r = (size_t)(m0 + ty * 8 + i);
        #pragma unroll
        for (int j = 0; j < 8; j++) {
            int col = n0 + tx * 8 + j;
            if (col < No) {
                size_t o = r * No + col;
                float v = acc[i][j];
                if (Cin) v += Cin[o];
                C[o] = v;
                cp[j] += v; cq[j] += v * v;
            }
        }
    }
    if (sums) {
        if (tid < TN) { csum[tid] = 0.f; csq[tid] = 0.f; }
        __syncthreads();
        #pragma unroll
        for (int j = 0; j < 8; j++) {
            atomicAdd(&csum[tx * 8 + j], cp[j]);
            atomicAdd(&csq[tx * 8 + j], cq[j]);
        }
        __syncthreads();
        if (tid < TN && n0 + tid < No) {
            atomicAdd(&sums[n0 + tid], csum[tid]);
            atomicAdd(&sqs[n0 + tid], csq[tid]);
        }
    }
}

// ---------------- bf16x3 tensor-core GEMM ----------------
// C(M x No) = [segmented A](M x nseg*F) @ W(nseg*F x No) [+ Cin] [+ BN stats]
// Split-precision: x = hi + lo (bf16 each); C ≈ Ah*Wh + Ah*Wl + Al*Wh.
// Block tile 128 x BN, 8 warps, warp tile WM x WN, mma m16n8k16.
// Requires F % 16 == 0, M % 128 == 0, No % BN == 0.

__device__ __forceinline__ void bsplit(float x, __nv_bfloat16& h, __nv_bfloat16& l) {
    h = __float2bfloat16_rn(x);
    l = __float2bfloat16_rn(x - __bfloat162float(h));
}

#define MMA_BF16(d, a, b) \
    asm volatile("mma.sync.aligned.m16n8k16.row.col.f32.bf16.bf16.f32 " \
        "{%0,%1,%2,%3},{%4,%5,%6,%7},{%8,%9},{%0,%1,%2,%3};" \
        : "+f"(d[0]), "+f"(d[1]), "+f"(d[2]), "+f"(d[3]) \
        : "r"(a[0]), "r"(a[1]), "r"(a[2]), "r"(a[3]), "r"(b[0]), "r"(b[1]))

template<int BN, int WM, int WN>
__global__ __launch_bounds__(256) void gemm_tc_k(
        const float* __restrict__ A0, const float* __restrict__ Zb,
        const float* __restrict__ W, const float* __restrict__ Cin,
        float* __restrict__ C, int F, int nseg, int No,
        float* __restrict__ sums, float* __restrict__ sqs) {
    constexpr int SA = 18;               // halfword row stride (pad for bank-free frags)
    constexpr int MT = WM / 16;
    constexpr int NT = WN / 8;
    constexpr int WNC = BN / WN;         // warps along n
    __shared__ alignas(16) __nv_bfloat16 Ah[128 * SA];
    __shared__ alignas(16) __nv_bfloat16 Al[128 * SA];
    __shared__ alignas(16) __nv_bfloat16 Wh[BN * SA];
    __shared__ alignas(16) __nv_bfloat16 Wl[BN * SA];
    __shared__ float csum[BN], csq[BN];

    int tid = threadIdx.x;
    int wid = tid >> 5, lane = tid & 31;
    int g = lane >> 2, t = lane & 3;
    int wm_id = wid / WNC, wn_id = wid % WNC;
    int m_base = wm_id * WM, n_base = wn_id * WN;
    int m0 = blockIdx.x * 128, n0 = blockIdx.y * BN;

    float acc[MT][NT][4];
    #pragma unroll
    for (int i = 0; i < MT; i++)
        #pragma unroll
        for (int j = 0; j < NT; j++)
            #pragma unroll
            for (int q = 0; q < 4; q++) acc[i][j][q] = 0.f;

    int Ktot = nseg * F;
    for (int kt = 0; kt < Ktot; kt += 16) {
        int seg = kt / F;                 // chunk lies in one segment (F % 16 == 0)
        int fk0 = kt - seg * F;
        const float* Ap = (seg == 0) ? A0 : (Zb + (size_t)(seg - 1) * SLICE);
        // stage A tile 128 x 16 (fp32 -> hi/lo bf16)
        #pragma unroll
        for (int i = 0; i < 2; i++) {
            int e = tid + i * 256;
            int mm = e >> 2, kk = (e & 3) * 4;
            float4 v = *(const float4*)&Ap[(size_t)(m0 + mm) * F + fk0 + kk];
            __nv_bfloat16 h0, l0, h1, l1, h2, l2, h3, l3;
            bsplit(v.x, h0, l0); bsplit(v.y, h1, l1);
            bsplit(v.z, h2, l2); bsplit(v.w, h3, l3);
            int o = mm * SA + kk;
            Ah[o] = h0; Ah[o + 1] = h1; Ah[o + 2] = h2; Ah[o + 3] = h3;
            Al[o] = l0; Al[o + 1] = l1; Al[o + 2] = l2; Al[o + 3] = l3;
        }
        // stage W tile 16 x BN transposed -> [n][k]
        constexpr int WT4 = 16 * BN / 4;
        #pragma unroll
        for (int i = 0; i < (WT4 + 255) / 256; i++) {
            int e = tid + i * 256;
            if (e < WT4) {
                int kk = e / (BN / 4), nn = (e % (BN / 4)) * 4;
                float4 v = *(const float4*)&W[(size_t)(kt + kk) * No + n0 + nn];
                __nv_bfloat16 h, l;
                bsplit(v.x, h, l); Wh[(nn + 0) * SA + kk] = h; Wl[(nn + 0) * SA + kk] = l;
                bsplit(v.y, h, l); Wh[(nn + 1) * SA + kk] = h; Wl[(nn + 1) * SA + kk] = l;
                bsplit(v.z, h, l); Wh[(nn + 2) * SA + kk] = h; Wl[(nn + 2) * SA + kk] = l;
                bsplit(v.w, h, l); Wh[(nn + 3) * SA + kk] = h; Wl[(nn + 3) * SA + kk] = l;
            }
        }
        __syncthreads();

        uint32_t af[MT][4], bh[NT][2], bl[NT][2];
        #pragma unroll
        for (int mt = 0; mt < MT; mt++) {
            int rb = (m_base + mt * 16 + g) * SA;
            af[mt][0] = *(const uint32_t*)&Ah[rb + 2 * t];
            af[mt][1] = *(const uint32_t*)&Ah[rb + 8 * SA + 2 * t];
            af[mt][2] = *(const uint32_t*)&Ah[rb + 2 * t + 8];
            af[mt][3] = *(const uint32_t*)&Ah[rb + 8 * SA + 2 * t + 8];
        }
        #pragma unroll
        for (int nt = 0; nt < NT; nt++) {
            int nb = (n_base + nt * 8 + g) * SA;
            bh[nt][0] = *(const uint32_t*)&Wh[nb + 2 * t];
            bh[nt][1] = *(const uint32_t*)&Wh[nb + 2 * t + 8];
            bl[nt][0] = *(const uint32_t*)&Wl[nb + 2 * t];
            bl[nt][1] = *(const uint32_t*)&Wl[nb + 2 * t + 8];
        }
        // Ah * Wh
        #pragma unroll
        for (int mt = 0; mt < MT; mt++)
            #pragma unroll
            for (int nt = 0; nt < NT; nt++)
                MMA_BF16(acc[mt][nt], af[mt], bh[nt]);
        // Ah * Wl
        #pragma unroll
        for (int mt = 0; mt < MT; mt++)
            #pragma unroll
            for (int nt = 0; nt < NT; nt++)
                MMA_BF16(acc[mt][nt], af[mt], bl[nt]);
        // Al * Wh
        #pragma unroll
        for (int mt = 0; mt < MT; mt++) {
            int rb = (m_base + mt * 16 + g) * SA;
            af[mt][0] = *(const uint32_t*)&Al[rb + 2 * t];
            af[mt][1] = *(const uint32_t*)&Al[rb + 8 * SA + 2 * t];
            af[mt][2] = *(const uint32_t*)&Al[rb + 2 * t + 8];
            af[mt][3] = *(const uint32_t*)&Al[rb + 8 * SA + 2 * t + 8];
        }
        #pragma unroll
        for (int mt = 0; mt < MT; mt++)
            #pragma unroll
            for (int nt = 0; nt < NT; nt++)
                MMA_BF16(acc[mt][nt], af[mt], bh[nt]);
        __syncthreads();
    }

    // epilogue: write C (+Cin), fused BN stats
    if (tid < BN) { csum[tid] = 0.f; csq[tid] = 0.f; }
    __syncthreads();
    float cp[NT][2], cq[NT][2];
    #pragma unroll
    for (int nt = 0; nt < NT; nt++) {
        cp[nt][0] = cp[nt][1] = 0.f; cq[nt][0] = cq[nt][1] = 0.f;
    }
    #pragma unroll
    for (int mt = 0; mt < MT; mt++) {
        size_t r0 = (size_t)(m0 + m_base + mt * 16 + g);
        size_t r1 = r0 + 8;
        #pragma unroll
        for (int nt = 0; nt < NT; nt++) {
            int col0 = n0 + n_base + nt * 8 + 2 * t;
            size_t o0 = r0 * No + col0;
            size_t o1 = r1 * No + col0;
            float v0 = acc[mt][nt][0], v1 = acc[mt][nt][1];
            float v2 = acc[mt][nt][2], v3 = acc[mt][nt][3];
            if (Cin) { v0 += Cin[o0]; v1 += Cin[o0 + 1]; v2 += Cin[o1]; v3 += Cin[o1 + 1]; }
            C[o0] = v0; C[o0 + 1] = v1; C[o1] = v2; C[o1 + 1] = v3;
            cp[nt][0] += v0 + v2; cp[nt][1] += v1 + v3;
            cq[nt][0] += v0 * v0 + v2 * v2; cq[nt][1] += v1 * v1 + v3 * v3;
        }
    }
    if (sums) {
        #pragma unroll
        for (int nt = 0; nt < NT; nt++) {
            int cb = n_base + nt * 8 + 2 * t;
            atomicAdd(&csum[cb], cp[nt][0]);     atomicAdd(&csq[cb], cq[nt][0]);
            atomicAdd(&csum[cb + 1], cp[nt][1]); atomicAdd(&csq[cb + 1], cq[nt][1]);
        }
        __syncthreads();
        if (tid < BN) {
            atomicAdd(&sums[n0 + tid], csum[tid]);
            atomicAdd(&sqs[n0 + tid], csq[tid]);
        }
    }
}

__global__ void zero_stats_k(float* s, float* q) {
    s[threadIdx.x] = 0.f; q[threadIdx.x] = 0.f;
}

__global__ void bn_apply_k(float* __restrict__ Y, const float* __restrict__ g,
                           const float* __restrict__ b, size_t total, int mask,
                           float invM, const float* __restrict__ sums,
                           const float* __restrict__ sqs) {
    size_t e = (size_t)blockIdx.x * blockDim.x + threadIdx.x;
    if (e >= total) return;
    int f = (int)(e & (size_t)mask);
    float mu = sums[f] * invM;
    float var = sqs[f] * invM - mu * mu;
    float v = (Y[e] - mu) * rsqrtf(var + 1e-5f) * g[f] + b[f];
    Y[e] = v > 0.f ? v : 0.f;
}

// 4:1 max pooling along n. In: (4*Nout, B, F) -> Out: (Nout, B, F)
__global__ void pool_k(const float* __restrict__ In, float* __restrict__ Out,
                       int Nout, int F) {
    int t = blockIdx.x * blockDim.x + threadIdx.x;
    int total = Nout * BG * F;
    if (t >= total) return;
    int f = t % F; int rb = t / F; int b = rb % BG; int n2 = rb / BG;
    size_t base = ((size_t)(n2 * 4) * BG + b) * F + f;
    size_t stride = (size_t)BG * F;
    float v = In[base];
    v = fmaxf(v, In[base + stride]);
    v = fmaxf(v, In[base + 2 * stride]);
    v = fmaxf(v, In[base + 3 * stride]);
    Out[t] = v;
}

// Out(n,b,0:Fu) = H(n/4,b,:) ; Out(n,b,Fu:Fu+Fs) = S(n,b,:)
__global__ void unpool_concat_k(const float* __restrict__ H, const float* __restrict__ S,
                                float* __restrict__ Out, int N, int Fu, int Fs) {
    int Fc = Fu + Fs;
    size_t total = (size_t)N * BG * Fc;
    size_t t = (size_t)blockIdx.x * blockDim.x + threadIdx.x;
    if (t >= total) return;
    int f = (int)(t % Fc);
    size_t rb = t / Fc;
    int b = (int)(rb % BG);
    int n = (int)(rb / BG);
    float v;
    if (f < Fu) v = H[(((size_t)(n >> 2)) * BG + b) * Fu + f];
    else        v = S[(((size_t)n) * BG + b) * Fs + (f - Fu)];
    Out[t] = v;
}

// C[r] = dot(X[r, 0:32], w) (+ Cin[r]). One warp per row.
__global__ void proj1_k(const float* __restrict__ X, const float* __restrict__ w,
                        const float* __restrict__ Cin, float* __restrict__ C, int M) {
    int gw = (int)((blockIdx.x * blockDim.x + threadIdx.x) >> 5);
    int lane = threadIdx.x & 31;
    if (gw >= M) return;
    float acc = X[(size_t)gw * 32 + lane] * w[lane];
    #pragma unroll
    for (int o = 16; o; o >>= 1) acc += __shfl_down_sync(0xffffffffu, acc, o);
    if (lane == 0) C[gw] = acc + (Cin ? Cin[gw] : 0.f);
}

// Y layout row = n*256 + bg  ->  out (4,1,8,8,768)
__global__ void reshape_out_k(const float* __restrict__ Y, float* __restrict__ out) {
    int t = blockIdx.x * blockDim.x + threadIdx.x;  // 196,608
    int n = t % 768;
    int r = t / 768;
    int hw = r & 63;
    int b0 = r >> 6;
    out[t] = Y[(size_t)n * BG + (size_t)b0 * 64 + hw];
}

// ---------------- host side ----------------

static void run_gemm(const float* A0, const float* Zb, const float* W, const float* Cin,
                     float* C, int M, int F, int nseg, int No, float* sums, float* sqs) {
    if (F % 16 == 0) {
        // tensor-core bf16x3 path
        if (No % 128 == 0) {
            dim3 g(M / 128, No / 128);
            gemm_tc_k<128, 64, 32><<<g, 256>>>(A0, Zb, W, Cin, C, F, nseg, No, sums, sqs);
        } else if (No == 64) {
            gemm_tc_k<64, 32, 32><<<M / 128, 256>>>(A0, Zb, W, Cin, C, F, nseg, No, sums, sqs);
        } else {  // No == 32
            gemm_tc_k<32, 32, 16><<<M / 128, 256>>>(A0, Zb, W, Cin, C, F, nseg, No, sums, sqs);
        }
        return;
    }
    // fp32 fallback (small F)
    if (No >= 128) {
        dim3 g(M / 128, (No + 127) / 128);
        gemm_k<128><<<g, 256>>>(A0, Zb, W, Cin, C, F, nseg, No, sums, sqs);
    } else if (No >= 64) {
        dim3 g(M / 128, 1);
        gemm_k<64><<<g, 128>>>(A0, Zb, W, Cin, C, F, nseg, No, sums, sqs);
    } else {
        dim3 g(M / 128, 1);
        gemm_k<32><<<g, 64>>>(A0, Zb, W, Cin, C, F, nseg, No, sums, sqs);
    }
}

extern "C" void kernel_launch(void* const* d_in, const int* in_sizes, int n_in,
                              void* d_out, int out_size) {
    const float* x = (const float*)d_in[0];

    float *A_, *B_, *Z_, *S3, *S2, *S1, *Wc, *sum_, *sq_, *cval;
    int *cidx, *cnnz;
    cudaGetSymbolAddress((void**)&A_,  g_A);
    cudaGetSymbolAddress((void**)&B_,  g_B);
    cudaGetSymbolAddress((void**)&Z_,  g_Z);
    cudaGetSymbolAddress((void**)&S3,  g_S3);
    cudaGetSymbolAddress((void**)&S2,  g_S2);
    cudaGetSymbolAddress((void**)&S1,  g_S1);
    cudaGetSymbolAddress((void**)&Wc,  g_Wc);
    cudaGetSymbolAddress((void**)&sum_, g_sum);
    cudaGetSymbolAddress((void**)&sq_,  g_sq);
    cudaGetSymbolAddress((void**)&cidx, g_cidx);
    cudaGetSymbolAddress((void**)&cval, g_cval);
    cudaGetSymbolAddress((void**)&cnnz, g_cnnz);

    build_all_k<<<8, 128>>>((const float*)d_in[1], (const float*)d_in[2],
                            (const float*)d_in[3], (const float*)d_in[4],
                            cidx, cval, cnnz);
    transpose_in_k<<<6144, 256>>>(x, A_);

    auto spmm1 = [&](int lvl, int N, int F, const float* in, float* out,
                     float alpha, const float* S) {
        int cols4 = BG * F / 4;
        int thr = cols4 < 256 ? cols4 : 256;
        dim3 gs(cols4 / thr, N);
        spmm_k<<<gs, thr>>>(cidx + lvl * 768 * MAXNNZ, cval + lvl * 768 * MAXNNZ,
                            cnnz + lvl * 768, cols4, (const float4*)in, (float4*)out,
                            alpha, (const float4*)S);
    };

    auto spmm3 = [&](int lvl, int N, int F, const float* in) {
        spmm1(lvl, N, F, in, Z_, 1.f, nullptr);
        spmm1(lvl, N, F, Z_, Z_ + SLICE, 2.f, in);
        spmm1(lvl, N, F, Z_ + SLICE, Z_ + 2 * SLICE, 2.f, Z_);
    };

    auto enc = [&](int lvl, int N, int F, int Fo, const float* w, const float* gg,
                   const float* bb, const float* in, float* out) {
        spmm3(lvl, N, F, in);
        int M = N * BG;
        zero_stats_k<<<1, 256>>>(sum_, sq_);
        run_gemm(in, Z_, w, nullptr, out, M, F, 4, Fo, sum_, sq_);
        size_t tot = (size_t)M * Fo;
        bn_apply_k<<<(unsigned)((tot + 255) / 256), 256>>>(out, gg, bb, tot, Fo - 1,
                                                           1.0f / (float)M, sum_, sq_);
    };

    auto deco = [&](int lvl, int N, int F, int Fo, const float* w, const float* gg,
                    const float* bb, const float* in, float* out) {
        int FFo = F * Fo;
        wcomb_k<<<(FFo + 255) / 256, 256>>>(w, Wc, FFo);
        int M = N * BG;
        float* Z0 = Z_; float* Z1 = Z_ + SLICE; float* Z2 = Z_ + 2 * SLICE;
        run_gemm(in, nullptr, Wc,           nullptr, Z0, M, F, 1, Fo, nullptr, nullptr);
        spmm1(lvl, N, Fo, Z0, Z1, 1.f, nullptr);
        run_gemm(in, nullptr, Wc + FFo,     Z1,      Z1, M, F, 1, Fo, nullptr, nullptr);
        spmm1(lvl, N, Fo, Z1, Z2, 1.f, nullptr);
        run_gemm(in, nullptr, Wc + 2 * FFo, Z2,      Z2, M, F, 1, Fo, nullptr, nullptr);
        spmm1(lvl, N, Fo, Z2, out, 1.f, nullptr);
        zero_stats_k<<<1, 256>>>(sum_, sq_);
        run_gemm(in, nullptr, Wc + 3 * FFo, out,     out, M, F, 1, Fo, sum_, sq_);
        size_t tot = (size_t)M * Fo;
        bn_apply_k<<<(unsigned)((tot + 255) / 256), 256>>>(out, gg, bb, tot, Fo - 1,
                                                           1.0f / (float)M, sum_, sq_);
    };

    const float* w_e3a = (const float*)d_in[5];
    const float* g_e3a_ = (const float*)d_in[6];  const float* b_e3a_ = (const float*)d_in[7];
    const float* w_e3b = (const float*)d_in[8];
    const float* g_e3b_ = (const float*)d_in[9];  const float* b_e3b_ = (const float*)d_in[10];
    const float* w_e2 = (const float*)d_in[11];
    const float* g_e2_ = (const float*)d_in[12];  const float* b_e2_ = (const float*)d_in[13];
    const float* w_e1 = (const float*)d_in[14];
    const float* g_e1_ = (const float*)d_in[15];  const float* b_e1_ = (const float*)d_in[16];
    const float* w_e0 = (const float*)d_in[17];
    const float* g_e0_ = (const float*)d_in[18];  const float* b_e0_ = (const float*)d_in[19];
    const float* w_d1 = (const float*)d_in[20];
    const float* g_d1_ = (const float*)d_in[21];  const float* b_d1_ = (const float*)d_in[22];
    const float* w_d2 = (const float*)d_in[23];
    const float* g_d2_ = (const float*)d_in[24];  const float* b_d2_ = (const float*)d_in[25];
    const float* w_d3 = (const float*)d_in[26];
    const float* g_d3_ = (const float*)d_in[27];  const float* b_d3_ = (const float*)d_in[28];
    const float* w_out = (const float*)d_in[29];

    // encoder
    enc(0, 768,   8,  32, w_e3a, g_e3a_, b_e3a_, A_, B_);  // fp32 path (F=8)
    enc(0, 768,  32,  64, w_e3b, g_e3b_, b_e3b_, B_, S3);
    pool_k<<<(192 * BG * 64 + 255) / 256, 256>>>(S3, A_, 192, 64);
    enc(1, 192,  64, 128, w_e2, g_e2_, b_e2_, A_, S2);
    pool_k<<<(48 * BG * 128 + 255) / 256, 256>>>(S2, A_, 48, 128);
    enc(2, 48,  128, 256, w_e1, g_e1_, b_e1_, A_, S1);
    pool_k<<<(12 * BG * 256 + 255) / 256, 256>>>(S1, A_, 12, 256);
    enc(3, 12,  256, 256, w_e0, g_e0_, b_e0_, A_, B_);
    // decoder (Horner order)
    unpool_concat_k<<<(48 * BG * 512 + 255) / 256, 256>>>(B_, S1, A_, 48, 256, 256);
    deco(2, 48,  512, 128, w_d1, g_d1_, b_d1_, A_, B_);
    unpool_concat_k<<<(192 * BG * 256 + 255) / 256, 256>>>(B_, S2, A_, 192, 128, 128);
    deco(1, 192, 256,  64, w_d2, g_d2_, b_d2_, A_, B_);
    unpool_concat_k<<<(768 * BG * 128 + 255) / 256, 256>>>(B_, S3, A_, 768, 64, 64);
    deco(0, 768, 128,  32, w_d3, g_d3_, b_d3_, A_, B_);

    // out layer (32 -> 1), Horner in 1-channel space
    {
        int M = 196608;
        wcomb_k<<<(32 * 1 + 255) / 256, 256>>>(w_out, Wc, 32);
        float* Z0 = Z_; float* Z1 = Z_ + SLICE; float* Z2 = Z_ + 2 * SLICE;
        int pb = (M * 32 + 255) / 256;
        proj1_k<<<pb, 256>>>(B_, Wc,      nullptr, Z0, M);
        spmm1(0, 768, 1, Z0, Z1, 1.f, nullptr);
        proj1_k<<<pb, 256>>>(B_, Wc + 32, Z1,      Z1, M);
        spmm1(0, 768, 1, Z1, Z2, 1.f, nullptr);
        proj1_k<<<pb, 256>>>(B_, Wc + 64, Z2,      Z2, M);
        spmm1(0, 768, 1, Z2, A_, 1.f, nullptr);
        proj1_k<<<pb, 256>>>(B_, Wc + 96, A_,      A_, M);
    }
    reshape_out_k<<<196608 / 256, 256>>>(A_, (float*)d_out);
}

// round 8
// speedup vs baseline: 1.9476x; 1.2061x over previous
#include <cuda_runtime.h>
#include <cuda_bf16.h>
#include <cstdint>
#include <cstddef>

#define MAXNNZ 40
#define BG 256
#define SLICE 25165824UL   // 768*256*128 floats (largest N*B*F slab)

// ---------------- static scratch (no allocation allowed) ----------------
__device__ float g_A[SLICE];                 // ping buffer (N,B,F)
__device__ float g_B[SLICE];                 // pong buffer
__device__ float g_Z[3*SLICE];               // Chebyshev / Horner temporaries
__device__ float g_S3[768*256*64];           // skip s3
__device__ float g_S2[192*256*128];          // skip s2
__device__ float g_S1[48*256*256];           // skip s1
__device__ float g_Wc[4*512*128];            // combined Horner weights (F x 4Fo)
__device__ int   g_cidx[4*768*MAXNNZ];       // ELL col indices per level
__device__ float g_cval[4*768*MAXNNZ];       // ELL values
__device__ int   g_cnnz[4*768];              // per-row nnz
__device__ float g_sum[8*256];               // BN channel sums (per layer)
__device__ float g_sq[8*256];                // BN channel sum-of-squares

// ---------------- kernels ----------------

__global__ void zero_all_k(float* s, float* q) {
    int i = blockIdx.x * blockDim.x + threadIdx.x;
    s[i] = 0.f; q[i] = 0.f;
}

// Extract ELL sparse structure for all 4 levels in one launch.
__global__ void build_all_k(const float* __restrict__ L3, const float* __restrict__ L2,
                            const float* __restrict__ L1, const float* __restrict__ L0,
                            int* __restrict__ idx, float* __restrict__ val,
                            int* __restrict__ nnz) {
    int t = blockIdx.x * blockDim.x + threadIdx.x;
    if (t >= 1020) return;
    int lvl, n, N;
    const float* L;
    if (t < 768)       { lvl = 0; n = t;        N = 768; L = L3; }
    else if (t < 960)  { lvl = 1; n = t - 768;  N = 192; L = L2; }
    else if (t < 1008) { lvl = 2; n = t - 960;  N = 48;  L = L1; }
    else               { lvl = 3; n = t - 1008; N = 12;  L = L0; }
    int base = (lvl * 768 + n) * MAXNNZ;
    int c = 0;
    for (int m = 0; m < N; m++) {
        float v = L[n * N + m];
        if (v != 0.0f && c < MAXNNZ) {
            idx[base + c] = m;
            val[base + c] = v;
            c++;
        }
    }
    nnz[lvl * 768 + n] = c;
}

// x (4,8,8,8,768) -> A layout (n, bg, c) with bg = b0*64 + hw
__global__ void transpose_in_k(const float* __restrict__ x, float* __restrict__ A) {
    int t = blockIdx.x * blockDim.x + threadIdx.x;  // 1,572,864 total
    int n = t % 768;
    int r = t / 768;
    int hw = r & 63; r >>= 6;
    int c = r & 7;  int b0 = r >> 3;
    A[((size_t)n * BG + (size_t)b0 * 64 + hw) * 8 + c] = x[t];
}

// Z[row,:] = alpha * (L X)[row,:] + beta * S[row,:]
__global__ void spmm_k(const int* __restrict__ idx, const float* __restrict__ val,
                       const int* __restrict__ nnz, int cols4,
                       const float4* __restrict__ X, float4* __restrict__ Z,
                       float alpha, float beta, const float4* __restrict__ S) {
    int row = blockIdx.y;
    int c = blockIdx.x * blockDim.x + threadIdx.x;
    __shared__ int   si[MAXNNZ];
    __shared__ float sv[MAXNNZ];
    __shared__ int   sn;
    int tid = threadIdx.x;
    if (tid < MAXNNZ) { si[tid] = idx[row * MAXNNZ + tid]; sv[tid] = val[row * MAXNNZ + tid]; }
    if (tid == 0) sn = nnz[row];
    __syncthreads();
    float4 acc = make_float4(0.f, 0.f, 0.f, 0.f);
    int nn = sn;
    #pragma unroll 4
    for (int j = 0; j < nn; j++) {
        float v = sv[j];
        float4 xv = __ldg(&X[(size_t)si[j] * cols4 + c]);
        acc.x += v * xv.x; acc.y += v * xv.y; acc.z += v * xv.z; acc.w += v * xv.w;
    }
    size_t o = (size_t)row * cols4 + c;
    float4 out;
    if (S) {
        float4 s = S[o];
        out = make_float4(alpha * acc.x + beta * s.x, alpha * acc.y + beta * s.y,
                          alpha * acc.z + beta * s.z, alpha * acc.w + beta * s.w);
    } else {
        out = make_float4(alpha * acc.x, alpha * acc.y, alpha * acc.z, alpha * acc.w);
    }
    Z[o] = out;
}

// Combined Horner weights, interleaved layout W'(F x 4Fo):
// W'[k][j*Fo+n] = coeff_j[k][n], coeffs: 4w3, 2w2, w1-3w3, w0-w2
__global__ void wcomb_k(const float* __restrict__ w, float* __restrict__ wc,
                        int F, int Fo) {
    int i = blockIdx.x * blockDim.x + threadIdx.x;
    int FFo = F * Fo;
    if (i >= FFo) return;
    int k = i / Fo, n = i % Fo;
    float w0 = w[i], w1 = w[FFo + i], w2 = w[2 * FFo + i], w3 = w[3 * FFo + i];
    float* row = wc + (size_t)k * 4 * Fo + n;
    row[0]        = 4.f * w3;
    row[Fo]       = 2.f * w2;
    row[2 * Fo]   = w1 - 3.f * w3;
    row[3 * Fo]   = w0 - w2;
}

// ---------------- fp32 fallback GEMM (e3a only, F=8) ----------------
template<int TN>
__global__ __launch_bounds__(2 * TN) void gemm_k(
        const float* __restrict__ A0, const float* __restrict__ Zb,
        const float* __restrict__ W, float* __restrict__ C,
        int F, int nseg, int No,
        float* __restrict__ sums, float* __restrict__ sqs) {
    __shared__ float As[8][132];
    __shared__ float Ws[8][TN + 4];
    __shared__ float csum[TN], csq[TN];
    const int NT = 2 * TN;
    int tid = threadIdx.x;
    int m0 = blockIdx.x * 128, n0 = blockIdx.y * TN;
    int tx = tid % (TN / 8), ty = tid / (TN / 8);
    float acc[8][8];
    #pragma unroll
    for (int i = 0; i < 8; i++)
        #pragma unroll
        for (int j = 0; j < 8; j++) acc[i][j] = 0.f;

    int Ktot = nseg * F;
    for (int kt = 0; kt < Ktot; kt += 8) {
        int seg = kt / F;
        int fk0 = kt - seg * F;
        const float* Ap = (seg == 0) ? A0 : (Zb + (size_t)(seg - 1) * SLICE);
        #pragma unroll
        for (int i = 0; i < 1024 / NT; i++) {
            int e = tid + i * NT;
            int mm = e >> 3, kk = e & 7;
            As[kk][mm] = Ap[(size_t)(m0 + mm) * F + fk0 + kk];
        }
        #pragma unroll
        for (int i = 0; i < 4; i++) {
            int e = tid + i * NT;
            int kk = e / TN, nn = e % TN;
            int col = n0 + nn;
            Ws[kk][nn] = (col < No) ? W[(size_t)(kt + kk) * No + col] : 0.f;
        }
        __syncthreads();
        #pragma unroll
        for (int kk = 0; kk < 8; kk++) {
            float4 a0v = *(const float4*)&As[kk][ty * 8];
            float4 a1v = *(const float4*)&As[kk][ty * 8 + 4];
            float4 b0v = *(const float4*)&Ws[kk][tx * 8];
            float4 b1v = *(const float4*)&Ws[kk][tx * 8 + 4];
            float av[8] = {a0v.x, a0v.y, a0v.z, a0v.w, a1v.x, a1v.y, a1v.z, a1v.w};
            float bv[8] = {b0v.x, b0v.y, b0v.z, b0v.w, b1v.x, b1v.y, b1v.z, b1v.w};
            #pragma unroll
            for (int i = 0; i < 8; i++)
                #pragma unroll
                for (int j = 0; j < 8; j++)
                    acc[i][j] += av[i] * bv[j];
        }
        __syncthreads();
    }

    float cp[8], cq[8];
    #pragma unroll
    for (int j = 0; j < 8; j++) { cp[j] = 0.f; cq[j] = 0.f; }
    #pragma unroll
    for (int i = 0; i < 8; i++) {
        size_t r = (size_t)(m0 + ty * 8 + i);
        #pragma unroll
        for (int j = 0; j < 8; j++) {
            int col = n0 + tx * 8 + j;
            if (col < No) {
                size_t o = r * No + col;
                float v = acc[i][j];
                C[o] = v;
                cp[j] += v; cq[j] += v * v;
            }
        }
    }
    if (sums) {
        if (tid < TN) { csum[tid] = 0.f; csq[tid] = 0.f; }
        __syncthreads();
        #pragma unroll
        for (int j = 0; j < 8; j++) {
            atomicAdd(&csum[tx * 8 + j], cp[j]);
            atomicAdd(&csq[tx * 8 + j], cq[j]);
        }
        __syncthreads();
        if (tid < TN && n0 + tid < No) {
            atomicAdd(&sums[n0 + tid], csum[tid]);
            atomicAdd(&sqs[n0 + tid], csq[tid]);
        }
    }
}

// ---------------- bf16x3 tensor-core GEMM ----------------
// Split-precision: x = hi + lo (bf16); C ≈ Ah*Wh + Ah*Wl + Al*Wh.
// If split_fo > 0: output column col = j*split_fo + off is scattered to
// C + j*psz + row*split_fo + off (4 separate slabs for Horner).

__device__ __forceinline__ void bsplit(float x, __nv_bfloat16& h, __nv_bfloat16& l) {
    h = __float2bfloat16_rn(x);
    l = __float2bfloat16_rn(x - __bfloat162float(h));
}

#define MMA_BF16(d, a, b) \
    asm volatile("mma.sync.aligned.m16n8k16.row.col.f32.bf16.bf16.f32 " \
        "{%0,%1,%2,%3},{%4,%5,%6,%7},{%8,%9},{%0,%1,%2,%3};" \
        : "+f"(d[0]), "+f"(d[1]), "+f"(d[2]), "+f"(d[3]) \
        : "r"(a[0]), "r"(a[1]), "r"(a[2]), "r"(a[3]), "r"(b[0]), "r"(b[1]))

template<int BN, int WM, int WN>
__global__ __launch_bounds__(256) void gemm_tc_k(
        const float* __restrict__ A0, const float* __restrict__ Zb,
        const float* __restrict__ W, float* __restrict__ C,
        int F, int nseg, int No,
        float* __restrict__ sums, float* __restrict__ sqs,
        int split_fo, size_t psz) {
    constexpr int SA = 18;
    constexpr int MT = WM / 16;
    constexpr int NT = WN / 8;
    constexpr int WNC = BN / WN;
    __shared__ alignas(16) __nv_bfloat16 Ah[128 * SA];
    __shared__ alignas(16) __nv_bfloat16 Al[128 * SA];
    __shared__ alignas(16) __nv_bfloat16 Wh[BN * SA];
    __shared__ alignas(16) __nv_bfloat16 Wl[BN * SA];
    __shared__ float csum[BN], csq[BN];

    int tid = threadIdx.x;
    int wid = tid >> 5, lane = tid & 31;
    int g = lane >> 2, t = lane & 3;
    int wm_id = wid / WNC, wn_id = wid % WNC;
    int m_base = wm_id * WM, n_base = wn_id * WN;
    int m0 = blockIdx.x * 128, n0 = blockIdx.y * BN;

    float acc[MT][NT][4];
    #pragma unroll
    for (int i = 0; i < MT; i++)
        #pragma unroll
        for (int j = 0; j < NT; j++)
            #pragma unroll
            for (int q = 0; q < 4; q++) acc[i][j][q] = 0.f;

    int Ktot = nseg * F;
    for (int kt = 0; kt < Ktot; kt += 16) {
        int seg = kt / F;
        int fk0 = kt - seg * F;
        const float* Ap = (seg == 0) ? A0 : (Zb + (size_t)(seg - 1) * SLICE);
        #pragma unroll
        for (int i = 0; i < 2; i++) {
            int e = tid + i * 256;
            int mm = e >> 2, kk = (e & 3) * 4;
            float4 v = *(const float4*)&Ap[(size_t)(m0 + mm) * F + fk0 + kk];
            __nv_bfloat16 h0, l0, h1, l1, h2, l2, h3, l3;
            bsplit(v.x, h0, l0); bsplit(v.y, h1, l1);
            bsplit(v.z, h2, l2); bsplit(v.w, h3, l3);
            int o = mm * SA + kk;
            Ah[o] = h0; Ah[o + 1] = h1; Ah[o + 2] = h2; Ah[o + 3] = h3;
            Al[o] = l0; Al[o + 1] = l1; Al[o + 2] = l2; Al[o + 3] = l3;
        }
        constexpr int WT4 = 16 * BN / 4;
        #pragma unroll
        for (int i = 0; i < (WT4 + 255) / 256; i++) {
            int e = tid + i * 256;
            if (e < WT4) {
                int kk = e / (BN / 4), nn = (e % (BN / 4)) * 4;
                float4 v = *(const float4*)&W[(size_t)(kt + kk) * No + n0 + nn];
                __nv_bfloat16 h, l;
                bsplit(v.x, h, l); Wh[(nn + 0) * SA + kk] = h; Wl[(nn + 0) * SA + kk] = l;
                bsplit(v.y, h, l); Wh[(nn + 1) * SA + kk] = h; Wl[(nn + 1) * SA + kk] = l;
                bsplit(v.z, h, l); Wh[(nn + 2) * SA + kk] = h; Wl[(nn + 2) * SA + kk] = l;
                bsplit(v.w, h, l); Wh[(nn + 3) * SA + kk] = h; Wl[(nn + 3) * SA + kk] = l;
            }
        }
        __syncthreads();

        uint32_t af[MT][4], bh[NT][2], bl[NT][2];
        #pragma unroll
        for (int mt = 0; mt < MT; mt++) {
            int rb = (m_base + mt * 16 + g) * SA;
            af[mt][0] = *(const uint32_t*)&Ah[rb + 2 * t];
            af[mt][1] = *(const uint32_t*)&Ah[rb + 8 * SA + 2 * t];
            af[mt][2] = *(const uint32_t*)&Ah[rb + 2 * t + 8];
            af[mt][3] = *(const uint32_t*)&Ah[rb + 8 * SA + 2 * t + 8];
        }
        #pragma unroll
        for (int nt = 0; nt < NT; nt++) {
            int nb = (n_base + nt * 8 + g) * SA;
            bh[nt][0] = *(const uint32_t*)&Wh[nb + 2 * t];
            bh[nt][1] = *(const uint32_t*)&Wh[nb + 2 * t + 8];
            bl[nt][0] = *(const uint32_t*)&Wl[nb + 2 * t];
            bl[nt][1] = *(const uint32_t*)&Wl[nb + 2 * t + 8];
        }
        #pragma unroll
        for (int mt = 0; mt < MT; mt++)
            #pragma unroll
            for (int nt = 0; nt < NT; nt++)
                MMA_BF16(acc[mt][nt], af[mt], bh[nt]);
        #pragma unroll
        for (int mt = 0; mt < MT; mt++)
            #pragma unroll
            for (int nt = 0; nt < NT; nt++)
                MMA_BF16(acc[mt][nt], af[mt], bl[nt]);
        #pragma unroll
        for (int mt = 0; mt < MT; mt++) {
            int rb = (m_base + mt * 16 + g) * SA;
            af[mt][0] = *(const uint32_t*)&Al[rb + 2 * t];
            af[mt][1] = *(const uint32_t*)&Al[rb + 8 * SA + 2 * t];
            af[mt][2] = *(const uint32_t*)&Al[rb + 2 * t + 8];
            af[mt][3] = *(const uint32_t*)&Al[rb + 8 * SA + 2 * t + 8];
        }
        #pragma unroll
        for (int mt = 0; mt < MT; mt++)
            #pragma unroll
            for (int nt = 0; nt < NT; nt++)
                MMA_BF16(acc[mt][nt], af[mt], bh[nt]);
        __syncthreads();
    }

    if (tid < BN) { csum[tid] = 0.f; csq[tid] = 0.f; }
    __syncthreads();
    float cp[NT][2], cq[NT][2];
    #pragma unroll
    for (int nt = 0; nt < NT; nt++) {
        cp[nt][0] = cp[nt][1] = 0.f; cq[nt][0] = cq[nt][1] = 0.f;
    }
    #pragma unroll
    for (int mt = 0; mt < MT; mt++) {
        size_t r0 = (size_t)(m0 + m_base + mt * 16 + g);
        size_t r1 = r0 + 8;
        #pragma unroll
        for (int nt = 0; nt < NT; nt++) {
            int col0 = n0 + n_base + nt * 8 + 2 * t;
            size_t o0, o1;
            if (split_fo) {
                int j = col0 / split_fo;
                int off = col0 - j * split_fo;
                o0 = (size_t)j * psz + r0 * split_fo + off;
                o1 = (size_t)j * psz + r1 * split_fo + off;
            } else {
                o0 = r0 * No + col0;
                o1 = r1 * No + col0;
            }
            float v0 = acc[mt][nt][0], v1 = acc[mt][nt][1];
            float v2 = acc[mt][nt][2], v3 = acc[mt][nt][3];
            C[o0] = v0; C[o0 + 1] = v1; C[o1] = v2; C[o1 + 1] = v3;
            cp[nt][0] += v0 + v2; cp[nt][1] += v1 + v3;
            cq[nt][0] += v0 * v0 + v2 * v2; cq[nt][1] += v1 * v1 + v3 * v3;
        }
    }
    if (sums) {
        #pragma unroll
        for (int nt = 0; nt < NT; nt++) {
            int cb = n_base + nt * 8 + 2 * t;
            atomicAdd(&csum[cb], cp[nt][0]);     atomicAdd(&csq[cb], cq[nt][0]);
            atomicAdd(&csum[cb + 1], cp[nt][1]); atomicAdd(&csq[cb + 1], cq[nt][1]);
        }
        __syncthreads();
        if (tid < BN) {
            atomicAdd(&sums[n0 + tid], csum[tid]);
            atomicAdd(&sqs[n0 + tid], csq[tid]);
        }
    }
}

// BN stats over a raw slab (decoder layers)
__global__ void bn_reduce_k(const float* __restrict__ Y, size_t total, int mask,
                            float* __restrict__ sums, float* __restrict__ sqs) {
    __shared__ float ss[256], qq[256];
    int tid = threadIdx.x;
    ss[tid] = 0.f; qq[tid] = 0.f;
    __syncthreads();
    for (size_t e = (size_t)blockIdx.x * blockDim.x + tid; e < total;
         e += (size_t)gridDim.x * blockDim.x) {
        float v = Y[e];
        int f = (int)(e & (size_t)mask);
        atomicAdd(&ss[f], v);
        atomicAdd(&qq[f], v * v);
    }
    __syncthreads();
    if (tid <= mask) { atomicAdd(&sums[tid], ss[tid]); atomicAdd(&sqs[tid], qq[tid]); }
}

// BN+ReLU in place (e3a only)
__global__ void bn_apply_k(float* __restrict__ Y, const float* __restrict__ g,
                           const float* __restrict__ b, size_t total, int mask,
                           float invM, const float* __restrict__ sums,
                           const float* __restrict__ sqs) {
    size_t e = (size_t)blockIdx.x * blockDim.x + threadIdx.x;
    if (e >= total) return;
    int f = (int)(e & (size_t)mask);
    float mu = sums[f] * invM;
    float var = sqs[f] * invM - mu * mu;
    float v = (Y[e] - mu) * rsqrtf(var + 1e-5f) * g[f] + b[f];
    Y[e] = v > 0.f ? v : 0.f;
}

// Fused BN+ReLU (in place on Y) + 4:1 max pool into P. Y: (4*Nout, B, F)
__global__ void bn_pool_k(float* __restrict__ Y, float* __restrict__ P,
                          const float* __restrict__ g, const float* __restrict__ b,
                          int Nout, int F, float invM,
                          const float* __restrict__ sums, const float* __restrict__ sqs) {
    int t = blockIdx.x * blockDim.x + threadIdx.x;
    int total = Nout * BG * F;
    if (t >= total) return;
    int f = t % F; int rb = t / F; int bb = rb % BG; int n2 = rb / BG;
    float mu = sums[f] * invM;
    float var = sqs[f] * invM - mu * mu;
    float sc = rsqrtf(var + 1e-5f) * g[f];
    float sh = b[f] - mu * sc;
    size_t base = ((size_t)(n2 * 4) * BG + bb) * F + f;
    size_t stride = (size_t)BG * F;
    float m = -1e30f;
    #pragma unroll
    for (int i = 0; i < 4; i++) {
        float v = Y[base + i * stride] * sc + sh;
        v = v > 0.f ? v : 0.f;
        Y[base + i * stride] = v;
        m = fmaxf(m, v);
    }
    P[t] = m;
}

// Out = concat(unpool(BN_ReLU(H)), S). H raw (N/4,B,Fu) with BN applied inline.
__global__ void unpool_concat_k(const float* __restrict__ H, const float* __restrict__ S,
                                float* __restrict__ Out, int N, int Fu, int Fs,
                                const float* __restrict__ g, const float* __restrict__ b,
                                float invM, const float* __restrict__ sums,
                                const float* __restrict__ sqs) {
    int Fc = Fu + Fs;
    size_t total = (size_t)N * BG * Fc;
    size_t t = (size_t)blockIdx.x * blockDim.x + threadIdx.x;
    if (t >= total) return;
    int f = (int)(t % Fc);
    size_t rb = t / Fc;
    int bb = (int)(rb % BG);
    int n = (int)(rb / BG);
    float v;
    if (f < Fu) {
        float x = H[(((size_t)(n >> 2)) * BG + bb) * Fu + f];
        float mu = sums[f] * invM;
        float var = sqs[f] * invM - mu * mu;
        v = (x - mu) * rsqrtf(var + 1e-5f) * g[f] + b[f];
        v = v > 0.f ? v : 0.f;
    } else {
        v = S[(((size_t)n) * BG + bb) * Fs + (f - Fu)];
    }
    Out[t] = v;
}

// Out layer projections: BN+ReLU(X row, d3 stats) then 4 dots with Horner weights.
// wc interleaved: wc[k*4+j]. P_j at P + j*psz, each (M x 1).
__global__ void proj4_k(const float* __restrict__ X, const float* __restrict__ wc,
                        float* __restrict__ P, int M, size_t psz,
                        const float* __restrict__ g, const float* __restrict__ b,
                        float invM, const float* __restrict__ sums,
                        const float* __restrict__ sqs) {
    int gw = (int)((blockIdx.x * blockDim.x + threadIdx.x) >> 5);
    int lane = threadIdx.x & 31;
    if (gw >= M) return;
    float x = X[(size_t)gw * 32 + lane];
    float mu = sums[lane] * invM;
    float var = sqs[lane] * invM - mu * mu;
    float xb = (x - mu) * rsqrtf(var + 1e-5f) * g[lane] + b[lane];
    xb = xb > 0.f ? xb : 0.f;
    float a0 = xb * wc[lane * 4 + 0];
    float a1 = xb * wc[lane * 4 + 1];
    float a2 = xb * wc[lane * 4 + 2];
    float a3 = xb * wc[lane * 4 + 3];
    #pragma unroll
    for (int o = 16; o; o >>= 1) {
        a0 += __shfl_down_sync(0xffffffffu, a0, o);
        a1 += __shfl_down_sync(0xffffffffu, a1, o);
        a2 += __shfl_down_sync(0xffffffffu, a2, o);
        a3 += __shfl_down_sync(0xffffffffu, a3, o);
    }
    if (lane == 0) {
        P[gw] = a0; P[psz + gw] = a1; P[2 * psz + gw] = a2; P[3 * psz + gw] = a3;
    }
}

// Y layout row = n*256 + bg  ->  out (4,1,8,8,768)
__global__ void reshape_out_k(const float* __restrict__ Y, float* __restrict__ out) {
    int t = blockIdx.x * blockDim.x + threadIdx.x;  // 196,608
    int n = t % 768;
    int r = t / 768;
    int hw = r & 63;
    int b0 = r >> 6;
    out[t] = Y[(size_t)n * BG + (size_t)b0 * 64 + hw];
}

// ---------------- host side ----------------

extern "C" void kernel_launch(void* const* d_in, const int* in_sizes, int n_in,
                              void* d_out, int out_size) {
    const float* x = (const float*)d_in[0];

    float *A_, *B_, *Z_, *S3, *S2, *S1, *Wc, *sum_, *sq_, *cval;
    int *cidx, *cnnz;
    cudaGetSymbolAddress((void**)&A_,  g_A);
    cudaGetSymbolAddress((void**)&B_,  g_B);
    cudaGetSymbolAddress((void**)&Z_,  g_Z);
    cudaGetSymbolAddress((void**)&S3,  g_S3);
    cudaGetSymbolAddress((void**)&S2,  g_S2);
    cudaGetSymbolAddress((void**)&S1,  g_S1);
    cudaGetSymbolAddress((void**)&Wc,  g_Wc);
    cudaGetSymbolAddress((void**)&sum_, g_sum);
    cudaGetSymbolAddress((void**)&sq_,  g_sq);
    cudaGetSymbolAddress((void**)&cidx, g_cidx);
    cudaGetSymbolAddress((void**)&cval, g_cval);
    cudaGetSymbolAddress((void**)&cnnz, g_cnnz);

    const float* w_e3a = (const float*)d_in[5];
    const float* g_e3a_ = (const float*)d_in[6];  const float* b_e3a_ = (const float*)d_in[7];
    const float* w_e3b = (const float*)d_in[8];
    const float* g_e3b_ = (const float*)d_in[9];  const float* b_e3b_ = (const float*)d_in[10];
    const float* w_e2 = (const float*)d_in[11];
    const float* g_e2_ = (const float*)d_in[12];  const float* b_e2_ = (const float*)d_in[13];
    const float* w_e1 = (const float*)d_in[14];
    const float* g_e1_ = (const float*)d_in[15];  const float* b_e1_ = (const float*)d_in[16];
    const float* w_e0 = (const float*)d_in[17];
    const float* g_e0_ = (const float*)d_in[18];  const float* b_e0_ = (const float*)d_in[19];
    const float* w_d1 = (const float*)d_in[20];
    const float* g_d1_ = (const float*)d_in[21];  const float* b_d1_ = (const float*)d_in[22];
    const float* w_d2 = (const float*)d_in[23];
    const float* g_d2_ = (const float*)d_in[24];  const float* b_d2_ = (const float*)d_in[25];
    const float* w_d3 = (const float*)d_in[26];
    const float* g_d3_ = (const float*)d_in[27];  const float* b_d3_ = (const float*)d_in[28];
    const float* w_out = (const float*)d_in[29];

    zero_all_k<<<8, 256>>>(sum_, sq_);
    build_all_k<<<8, 128>>>((const float*)d_in[1], (const float*)d_in[2],
                            (const float*)d_in[3], (const float*)d_in[4],
                            cidx, cval, cnnz);
    transpose_in_k<<<6144, 256>>>(x, A_);

    auto spmm1 = [&](int lvl, int N, int F, const float* in, float* out,
                     float alpha, float beta, const float* S) {
        int cols4 = BG * F / 4;
        int thr = cols4 < 256 ? cols4 : 256;
        dim3 gs(cols4 / thr, N);
        spmm_k<<<gs, thr>>>(cidx + lvl * 768 * MAXNNZ, cval + lvl * 768 * MAXNNZ,
                            cnnz + lvl * 768, cols4, (const float4*)in, (float4*)out,
                            alpha, beta, (const float4*)S);
    };

    auto spmm3 = [&](int lvl, int N, int F, const float* in) {
        spmm1(lvl, N, F, in, Z_, 1.f, 0.f, nullptr);
        spmm1(lvl, N, F, Z_, Z_ + SLICE, 2.f, -1.f, in);
        spmm1(lvl, N, F, Z_ + SLICE, Z_ + 2 * SLICE, 2.f, -1.f, Z_);
    };

    auto run_tc = [&](const float* A0, const float* Zb, const float* W, float* C,
                      int M, int F, int nseg, int No, float* su, float* sq,
                      int split_fo, size_t psz) {
        if (No % 128 == 0) {
            dim3 g(M / 128, No / 128);
            gemm_tc_k<128, 64, 32><<<g, 256>>>(A0, Zb, W, C, F, nseg, No, su, sq,
                                               split_fo, psz);
        } else {  // No == 64
            gemm_tc_k<64, 32, 32><<<M / 128, 256>>>(A0, Zb, W, C, F, nseg, No, su, sq,
                                                    split_fo, psz);
        }
    };

    // -------- encoder --------
    // e3a (fp32 path, F=8), stats idx 0
    spmm3(0, 768, 8, A_);
    {
        dim3 g(196608 / 128, 1);
        gemm_k<32><<<g, 64>>>(A_, Z_, w_e3a, B_, 8, 4, 32, sum_ + 0, sq_ + 0);
        bn_apply_k<<<(196608 * 32 + 255) / 256, 256>>>(B_, g_e3a_, b_e3a_,
            (size_t)196608 * 32, 31, 1.0f / 196608.f, sum_ + 0, sq_ + 0);
    }
    // e3b, stats idx 1; raw -> S3, then fused bn+pool -> A_
    spmm3(0, 768, 32, B_);
    run_tc(B_, Z_, w_e3b, S3, 196608, 32, 4, 64, sum_ + 256, sq_ + 256, 0, 0);
    bn_pool_k<<<(192 * BG * 64 + 255) / 256, 256>>>(S3, A_, g_e3b_, b_e3b_, 192, 64,
        1.0f / 196608.f, sum_ + 256, sq_ + 256);
    // e2, stats idx 2
    spmm3(1, 192, 64, A_);
    run_tc(A_, Z_, w_e2, S2, 49152, 64, 4, 128, sum_ + 512, sq_ + 512, 0, 0);
    bn_pool_k<<<(48 * BG * 128 + 255) / 256, 256>>>(S2, A_, g_e2_, b_e2_, 48, 128,
        1.0f / 49152.f, sum_ + 512, sq_ + 512);
    // e1, stats idx 3
    spmm3(2, 48, 128, A_);
    run_tc(A_, Z_, w_e1, S1, 12288, 128, 4, 256, sum_ + 768, sq_ + 768, 0, 0);
    bn_pool_k<<<(12 * BG * 256 + 255) / 256, 256>>>(S1, A_, g_e1_, b_e1_, 12, 256,
        1.0f / 12288.f, sum_ + 768, sq_ + 768);
    // e0, stats idx 4 (BN applied later inline in unpool_concat)
    spmm3(3, 12, 256, A_);
    run_tc(A_, Z_, w_e0, B_, 3072, 256, 4, 256, sum_ + 1024, sq_ + 1024, 0, 0);

    // -------- decoder (Horner, single-pass 4-output GEMM) --------
    auto deco = [&](int lvl, int N, int F, int Fo, const float* w,
                    const float* in, float* out, float* su, float* sq) {
        int M = N * BG;
        size_t PS = (size_t)M * Fo;
        wcomb_k<<<(F * Fo + 255) / 256, 256>>>(w, Wc, F, Fo);
        run_tc(in, nullptr, Wc, Z_, M, F, 1, 4 * Fo, nullptr, nullptr, Fo, PS);
        spmm1(lvl, N, Fo, Z_,          Z_ + PS,     1.f, 1.f, Z_ + PS);
        spmm1(lvl, N, Fo, Z_ + PS,     Z_ + 2 * PS, 1.f, 1.f, Z_ + 2 * PS);
        spmm1(lvl, N, Fo, Z_ + 2 * PS, out,         1.f, 1.f, Z_ + 3 * PS);
        bn_reduce_k<<<512, 256>>>(out, (size_t)M * Fo, Fo - 1, su, sq);
    };

    // d1: concat(unpool(BN(e0)), S1) -> A_; deco -> B_ raw, stats idx 5
    unpool_concat_k<<<(48 * BG * 512 + 255) / 256, 256>>>(B_, S1, A_, 48, 256, 256,
        g_e0_, b_e0_, 1.0f / 3072.f, sum_ + 1024, sq_ + 1024);
    deco(2, 48, 512, 128, w_d1, A_, B_, sum_ + 1280, sq_ + 1280);
    // d2
    unpool_concat_k<<<(192 * BG * 256 + 255) / 256, 256>>>(B_, S2, A_, 192, 128, 128,
        g_d1_, b_d1_, 1.0f / 12288.f, sum_ + 1280, sq_ + 1280);
    deco(1, 192, 256, 64, w_d2, A_, B_, sum_ + 1536, sq_ + 1536);
    // d3
    unpool_concat_k<<<(768 * BG * 128 + 255) / 256, 256>>>(B_, S3, A_, 768, 64, 64,
        g_d2_, b_d2_, 1.0f / 49152.f, sum_ + 1536, sq_ + 1536);
    deco(0, 768, 128, 32, w_d3, A_, B_, sum_ + 1792, sq_ + 1792);

    // -------- out layer (32 -> 1), BN(d3) fused into projection --------
    {
        int M = 196608;
        size_t PS = (size_t)M;
        wcomb_k<<<1, 32>>>(w_out, Wc, 32, 1);
        proj4_k<<<(M * 32 + 255) / 256, 256>>>(B_, Wc, Z_, M, PS,
            g_d3_, b_d3_, 1.0f / 196608.f, sum_ + 1792, sq_ + 1792);
        spmm1(0, 768, 1, Z_,          Z_ + PS,     1.f, 1.f, Z_ + PS);
        spmm1(0, 768, 1, Z_ + PS,     Z_ + 2 * PS, 1.f, 1.f, Z_ + 2 * PS);
        spmm1(0, 768, 1, Z_ + 2 * PS, A_,          1.f, 1.f, Z_ + 3 * PS);
    }
    reshape_out_k<<<196608 / 256, 256>>>(A_, (float*)d_out);
}

// round 9
// speedup vs baseline: 2.2870x; 1.1743x over previous
#include <cuda_runtime.h>
#include <cuda_bf16.h>
#include <cstdint>
#include <cstddef>

#define MAXNNZ 40
#define BG 256
#define SLICE 25165824UL   // 768*256*128 floats (largest N*B*F slab)

// Wc offsets (floats): d1 512x512, d2 256x256, d3 128x128, out 32x4
#define W1OFF 0
#define W2OFF 262144
#define W3OFF 327680
#define W4OFF 344064

// ---------------- static scratch (no allocation allowed) ----------------
__device__ float g_A[SLICE];                 // ping buffer (N,B,F)
__device__ float g_B[SLICE];                 // pong buffer
__device__ float g_Z[3*SLICE];               // Chebyshev / Horner temporaries
__device__ float g_S3[768*256*64];           // skip s3
__device__ float g_S2[192*256*128];          // skip s2
__device__ float g_S1[48*256*256];           // skip s1
__device__ float g_Wc[360448];               // combined Horner weights (all layers)
__device__ int   g_cidx[4*768*MAXNNZ];       // ELL col indices per level
__device__ float g_cval[4*768*MAXNNZ];       // ELL values
__device__ int   g_cnnz[4*768];              // per-row nnz
__device__ float g_sum[8*256];               // BN channel sums (per layer)
__device__ float g_sq[8*256];                // BN channel sum-of-squares

// ---------------- small kernels ----------------

__global__ void zero_all_k(float* s, float* q) {
    int i = blockIdx.x * blockDim.x + threadIdx.x;
    s[i] = 0.f; q[i] = 0.f;
}

__global__ void build_all_k(const float* __restrict__ L3, const float* __restrict__ L2,
                            const float* __restrict__ L1, const float* __restrict__ L0,
                            int* __restrict__ idx, float* __restrict__ val,
                            int* __restrict__ nnz) {
    int t = blockIdx.x * blockDim.x + threadIdx.x;
    if (t >= 1020) return;
    int lvl, n, N;
    const float* L;
    if (t < 768)       { lvl = 0; n = t;        N = 768; L = L3; }
    else if (t < 960)  { lvl = 1; n = t - 768;  N = 192; L = L2; }
    else if (t < 1008) { lvl = 2; n = t - 960;  N = 48;  L = L1; }
    else               { lvl = 3; n = t - 1008; N = 12;  L = L0; }
    int base = (lvl * 768 + n) * MAXNNZ;
    int c = 0;
    for (int m = 0; m < N; m++) {
        float v = L[n * N + m];
        if (v != 0.0f && c < MAXNNZ) {
            idx[base + c] = m;
            val[base + c] = v;
            c++;
        }
    }
    nnz[lvl * 768 + n] = c;
}

// x (4,8,8,8,768) -> A layout (n, bg, c) with bg = b0*64 + hw
__global__ void transpose_in_k(const float* __restrict__ x, float* __restrict__ A) {
    int t = blockIdx.x * blockDim.x + threadIdx.x;
    int n = t % 768;
    int r = t / 768;
    int hw = r & 63; r >>= 6;
    int c = r & 7;  int b0 = r >> 3;
    A[((size_t)n * BG + (size_t)b0 * 64 + hw) * 8 + c] = x[t];
}

// All Horner weight combos in one launch.
// Layers: (F,Fo,off,w): (512,128,W1OFF,w_d1) (256,64,W2OFF,w_d2)
//         (128,32,W3OFF,w_d3) (32,1,W4OFF,w_out)
__global__ void wcomb_all_k(const float* __restrict__ w1, const float* __restrict__ w2,
                            const float* __restrict__ w3, const float* __restrict__ w4,
                            float* __restrict__ wc) {
    int i = blockIdx.x * blockDim.x + threadIdx.x;
    const float* w; int Fo, off, r, FFo;
    if (i < 65536)      { w = w1; Fo = 128; off = W1OFF; r = i;         FFo = 65536; }
    else if (i < 81920) { w = w2; Fo = 64;  off = W2OFF; r = i - 65536; FFo = 16384; }
    else if (i < 86016) { w = w3; Fo = 32;  off = W3OFF; r = i - 81920; FFo = 4096;  }
    else if (i < 86048) { w = w4; Fo = 1;   off = W4OFF; r = i - 86016; FFo = 32;    }
    else return;
    int k = r / Fo, n = r - (r / Fo) * Fo;
    float w0 = w[r], wa = w[FFo + r], wb = w[2 * FFo + r], wd = w[3 * FFo + r];
    float* row = wc + off + (size_t)k * 4 * Fo + n;
    row[0]      = 4.f * wd;
    row[Fo]     = 2.f * wb;
    row[2 * Fo] = wa - 3.f * wd;
    row[3 * Fo] = w0 - wb;
}

// Z[row,:] = alpha * (L X)[row,:] + beta * S[row,:]  [+ fused BN stats]
__global__ void spmm_k(const int* __restrict__ idx, const float* __restrict__ val,
                       const int* __restrict__ nnz, int cols4,
                       const float4* __restrict__ X, float4* __restrict__ Z,
                       float alpha, float beta, const float4* __restrict__ S,
                       float* __restrict__ sums, float* __restrict__ sqs, int chmask) {
    int row = blockIdx.y;
    int c = blockIdx.x * blockDim.x + threadIdx.x;
    __shared__ int   si[MAXNNZ];
    __shared__ float sv[MAXNNZ];
    __shared__ int   sn;
    __shared__ float csum[256], csq[256];
    int tid = threadIdx.x;
    if (tid < MAXNNZ) { si[tid] = idx[row * MAXNNZ + tid]; sv[tid] = val[row * MAXNNZ + tid]; }
    if (tid == 0) sn = nnz[row];
    if (sums) { csum[tid] = 0.f; csq[tid] = 0.f; }
    __syncthreads();
    float4 acc = make_float4(0.f, 0.f, 0.f, 0.f);
    int nn = sn;
    #pragma unroll 4
    for (int j = 0; j < nn; j++) {
        float v = sv[j];
        float4 xv = __ldg(&X[(size_t)si[j] * cols4 + c]);
        acc.x += v * xv.x; acc.y += v * xv.y; acc.z += v * xv.z; acc.w += v * xv.w;
    }
    size_t o = (size_t)row * cols4 + c;
    float4 out;
    if (S) {
        float4 s = S[o];
        out = make_float4(alpha * acc.x + beta * s.x, alpha * acc.y + beta * s.y,
                          alpha * acc.z + beta * s.z, alpha * acc.w + beta * s.w);
    } else {
        out = make_float4(alpha * acc.x, alpha * acc.y, alpha * acc.z, alpha * acc.w);
    }
    Z[o] = out;
    if (sums) {
        int ch0 = (c * 4) & chmask;
        atomicAdd(&csum[ch0],     out.x); atomicAdd(&csq[ch0],     out.x * out.x);
        atomicAdd(&csum[ch0 + 1], out.y); atomicAdd(&csq[ch0 + 1], out.y * out.y);
        atomicAdd(&csum[ch0 + 2], out.z); atomicAdd(&csq[ch0 + 2], out.z * out.z);
        atomicAdd(&csum[ch0 + 3], out.w); atomicAdd(&csq[ch0 + 3], out.w * out.w);
        __syncthreads();
        if (tid <= chmask) { atomicAdd(&sums[tid], csum[tid]); atomicAdd(&sqs[tid], csq[tid]); }
    }
}

// ---------------- bf16x3 tensor-core GEMM, double-buffered ----------------
// Plain: A = segments {A0, Zb+k*SLICE} (nseg segments of width F), Ktot = nseg*F.
// Concat: A row m = [ BN_ReLU(H[(n>>2)*BG+bg, 0:Fu]) | S[n*BG+bg, 0:Fs] ], Ktot = Fu+Fs.
// split_fo > 0: column col -> C + (col/split_fo)*psz + row*split_fo + col%split_fo.

__device__ __forceinline__ void bsplit(float x, __nv_bfloat16& h, __nv_bfloat16& l) {
    h = __float2bfloat16_rn(x);
    l = __float2bfloat16_rn(x - __bfloat162float(h));
}

#define MMA_BF16(d, a, b) \
    asm volatile("mma.sync.aligned.m16n8k16.row.col.f32.bf16.bf16.f32 " \
        "{%0,%1,%2,%3},{%4,%5,%6,%7},{%8,%9},{%0,%1,%2,%3};" \
        : "+f"(d[0]), "+f"(d[1]), "+f"(d[2]), "+f"(d[3]) \
        : "r"(a[0]), "r"(a[1]), "r"(a[2]), "r"(a[3]), "r"(b[0]), "r"(b[1]))

template<int BN, int WM, int WN, bool CONCAT>
__global__ __launch_bounds__(256) void gemm_tc_k(
        const float* __restrict__ A0, const float* __restrict__ Zb,
        const float* __restrict__ W, float* __restrict__ C,
        int F, int lgF, int No,
        float* __restrict__ sums, float* __restrict__ sqs,
        int split_fo, size_t psz,
        int Fu, int Fs,
        const float* __restrict__ bng, const float* __restrict__ bnb,
        const float* __restrict__ bnsums, const float* __restrict__ bnsqs,
        float bninvM, int Ktot) {
    constexpr int SA = 18;
    constexpr int MT = WM / 16;
    constexpr int NT = WN / 8;
    constexpr int WNC = BN / WN;
    constexpr int WT4 = 16 * BN / 4;
    constexpr int WREG = (WT4 + 255) / 256;
    __shared__ alignas(16) __nv_bfloat16 Ah[2][128 * SA];
    __shared__ alignas(16) __nv_bfloat16 Al[2][128 * SA];
    __shared__ alignas(16) __nv_bfloat16 Wh[2][BN * SA];
    __shared__ alignas(16) __nv_bfloat16 Wl[2][BN * SA];
    __shared__ float csum[BN], csq[BN];
    __shared__ float scs[256], shs[256];

    int tid = threadIdx.x;
    int wid = tid >> 5, lane = tid & 31;
    int g = lane >> 2, t = lane & 3;
    int wm_id = wid / WNC, wn_id = wid % WNC;
    int m_base = wm_id * WM, n_base = wn_id * WN;
    int m0 = blockIdx.x * 128, n0 = blockIdx.y * BN;

    if (CONCAT && tid < Fu) {
        float mu = bnsums[tid] * bninvM;
        float var = bnsqs[tid] * bninvM - mu * mu;
        float sc = rsqrtf(var + 1e-5f) * bng[tid];
        scs[tid] = sc; shs[tid] = bnb[tid] - mu * sc;
    }

    float acc[MT][NT][4];
    #pragma unroll
    for (int i = 0; i < MT; i++)
        #pragma unroll
        for (int j = 0; j < NT; j++)
            #pragma unroll
            for (int q = 0; q < 4; q++) acc[i][j][q] = 0.f;

    auto ldA = [&](int kt, float4* aR) {
        #pragma unroll
        for (int i = 0; i < 2; i++) {
            int e = tid + i * 256;
            int mm = e >> 2, kk4 = (e & 3) * 4;
            int gf = kt + kk4;
            const float* p;
            if (CONCAT) {
                int m = m0 + mm; int n = m >> 8; int bg = m & 255;
                if (gf < Fu) p = &A0[((size_t)((n >> 2) << 8) + bg) * Fu + gf];
                else         p = &Zb[((size_t)(n << 8) + bg) * Fs + (gf - Fu)];
            } else {
                int seg = gf >> lgF;
                int fk = gf - (seg << lgF);
                const float* Ap = (seg == 0) ? A0 : (Zb + (size_t)(seg - 1) * SLICE);
                p = &Ap[(size_t)(m0 + mm) * F + fk];
            }
            aR[i] = __ldg((const float4*)p);
        }
    };
    auto ldW = [&](int kt, float4* wR) {
        #pragma unroll
        for (int i = 0; i < WREG; i++) {
            int e = tid + i * 256;
            if (e < WT4) {
                int kk = e / (BN / 4), nnq = (e % (BN / 4)) * 4;
                wR[i] = __ldg((const float4*)&W[(size_t)(kt + kk) * No + n0 + nnq]);
            }
        }
    };
    auto stA = [&](int kt, const float4* aR, int buf) {
        #pragma unroll
        for (int i = 0; i < 2; i++) {
            int e = tid + i * 256;
            int mm = e >> 2, kk4 = (e & 3) * 4;
            float4 v = aR[i];
            if (CONCAT) {
                int gf = kt + kk4;
                if (gf < Fu) {
                    v.x = fmaxf(v.x * scs[gf]     + shs[gf],     0.f);
                    v.y = fmaxf(v.y * scs[gf + 1] + shs[gf + 1], 0.f);
                    v.z = fmaxf(v.z * scs[gf + 2] + shs[gf + 2], 0.f);
                    v.w = fmaxf(v.w * scs[gf + 3] + shs[gf + 3], 0.f);
                }
            }
            int o = mm * SA + kk4;
            __nv_bfloat16 h, l;
            bsplit(v.x, h, l); Ah[buf][o]     = h; Al[buf][o]     = l;
            bsplit(v.y, h, l); Ah[buf][o + 1] = h; Al[buf][o + 1] = l;
            bsplit(v.z, h, l); Ah[buf][o + 2] = h; Al[buf][o + 2] = l;
            bsplit(v.w, h, l); Ah[buf][o + 3] = h; Al[buf][o + 3] = l;
        }
    };
    auto stW = [&](const float4* wR, int buf) {
        #pragma unroll
        for (int i = 0; i < WREG; i++) {
            int e = tid + i * 256;
            if (e < WT4) {
                int kk = e / (BN / 4), nnq = (e % (BN / 4)) * 4;
                float4 v = wR[i];
                __nv_bfloat16 h, l;
                bsplit(v.x, h, l); Wh[buf][(nnq + 0) * SA + kk] = h; Wl[buf][(nnq + 0) * SA + kk] = l;
                bsplit(v.y, h, l); Wh[buf][(nnq + 1) * SA + kk] = h; Wl[buf][(nnq + 1) * SA + kk] = l;
                bsplit(v.z, h, l); Wh[buf][(nnq + 2) * SA + kk] = h; Wl[buf][(nnq + 2) * SA + kk] = l;
                bsplit(v.w, h, l); Wh[buf][(nnq + 3) * SA + kk] = h; Wl[buf][(nnq + 3) * SA + kk] = l;
            }
        }
    };

    float4 aR[2], wR[WREG], aR2[2], wR2[WREG];
    ldA(0, aR); ldW(0, wR);
    __syncthreads();          // scs visible
    stA(0, aR, 0); stW(wR, 0);
    __syncthreads();
    int buf = 0;
    for (int kt = 0; kt < Ktot; kt += 16) {
        bool nb = (kt + 16) < Ktot;
        if (nb) { ldA(kt + 16, aR2); ldW(kt + 16, wR2); }

        uint32_t af[MT][4], bhf[NT][2], blf[NT][2];
        #pragma unroll
        for (int mt = 0; mt < MT; mt++) {
            int rb = (m_base + mt * 16 + g) * SA;
            af[mt][0] = *(const uint32_t*)&Ah[buf][rb + 2 * t];
            af[mt][1] = *(const uint32_t*)&Ah[buf][rb + 8 * SA + 2 * t];
            af[mt][2] = *(const uint32_t*)&Ah[buf][rb + 2 * t + 8];
            af[mt][3] = *(const uint32_t*)&Ah[buf][rb + 8 * SA + 2 * t + 8];
        }
        #pragma unroll
        for (int nt = 0; nt < NT; nt++) {
            int nb2 = (n_base + nt * 8 + g) * SA;
            bhf[nt][0] = *(const uint32_t*)&Wh[buf][nb2 + 2 * t];
            bhf[nt][1] = *(const uint32_t*)&Wh[buf][nb2 + 2 * t + 8];
            blf[nt][0] = *(const uint32_t*)&Wl[buf][nb2 + 2 * t];
            blf[nt][1] = *(const uint32_t*)&Wl[buf][nb2 + 2 * t + 8];
        }
        #pragma unroll
        for (int mt = 0; mt < MT; mt++)
            #pragma unroll
            for (int nt = 0; nt < NT; nt++)
                MMA_BF16(acc[mt][nt], af[mt], bhf[nt]);
        #pragma unroll
        for (int mt = 0; mt < MT; mt++)
            #pragma unroll
            for (int nt = 0; nt < NT; nt++)
                MMA_BF16(acc[mt][nt], af[mt], blf[nt]);
        #pragma unroll
        for (int mt = 0; mt < MT; mt++) {
            int rb = (m_base + mt * 16 + g) * SA;
            af[mt][0] = *(const uint32_t*)&Al[buf][rb + 2 * t];
            af[mt][1] = *(const uint32_t*)&Al[buf][rb + 8 * SA + 2 * t];
            af[mt][2] = *(const uint32_t*)&Al[buf][rb + 2 * t + 8];
            af[mt][3] = *(const uint32_t*)&Al[buf][rb + 8 * SA + 2 * t + 8];
        }
        #pragma unroll
        for (int mt = 0; mt < MT; mt++)
            #pragma unroll
            for (int nt = 0; nt < NT; nt++)
                MMA_BF16(acc[mt][nt], af[mt], bhf[nt]);

        if (nb) { stA(kt + 16, aR2, buf ^ 1); stW(wR2, buf ^ 1); }
        __syncthreads();
        buf ^= 1;
    }

    // epilogue: write C, fused BN stats
    if (tid < BN) { csum[tid] = 0.f; csq[tid] = 0.f; }
    __syncthreads();
    float cp[NT][2], cq[NT][2];
    #pragma unroll
    for (int nt = 0; nt < NT; nt++) {
        cp[nt][0] = cp[nt][1] = 0.f; cq[nt][0] = cq[nt][1] = 0.f;
    }
    #pragma unroll
    for (int mt = 0; mt < MT; mt++) {
        size_t r0 = (size_t)(m0 + m_base + mt * 16 + g);
        size_t r1 = r0 + 8;
        #pragma unroll
        for (int nt = 0; nt < NT; nt++) {
            int col0 = n0 + n_base + nt * 8 + 2 * t;
            size_t o0, o1;
            if (split_fo) {
                int j = col0 / split_fo;
                int off = col0 - j * split_fo;
                o0 = (size_t)j * psz + r0 * split_fo + off;
                o1 = (size_t)j * psz + r1 * split_fo + off;
            } else {
                o0 = r0 * No + col0;
                o1 = r1 * No + col0;
            }
            float v0 = acc[mt][nt][0], v1 = acc[mt][nt][1];
            float v2 = acc[mt][nt][2], v3 = acc[mt][nt][3];
            C[o0] = v0; C[o0 + 1] = v1; C[o1] = v2; C[o1 + 1] = v3;
            cp[nt][0] += v0 + v2; cp[nt][1] += v1 + v3;
            cq[nt][0] += v0 * v0 + v2 * v2; cq[nt][1] += v1 * v1 + v3 * v3;
        }
    }
    if (sums) {
        #pragma unroll
        for (int nt = 0; nt < NT; nt++) {
            int cb = n_base + nt * 8 + 2 * t;
            atomicAdd(&csum[cb], cp[nt][0]);     atomicAdd(&csq[cb], cq[nt][0]);
            atomicAdd(&csum[cb + 1], cp[nt][1]); atomicAdd(&csq[cb + 1], cq[nt][1]);
        }
        __syncthreads();
        if (tid < BN) {
            atomicAdd(&sums[n0 + tid], csum[tid]);
            atomicAdd(&sqs[n0 + tid], csq[tid]);
        }
    }
}

// BN+ReLU in place (e3a only)
__global__ void bn_apply_k(float* __restrict__ Y, const float* __restrict__ g,
                           const float* __restrict__ b, size_t total, int mask,
                           float invM, const float* __restrict__ sums,
                           const float* __restrict__ sqs) {
    size_t e = (size_t)blockIdx.x * blockDim.x + threadIdx.x;
    if (e >= total) return;
    int f = (int)(e & (size_t)mask);
    float mu = sums[f] * invM;
    float var = sqs[f] * invM - mu * mu;
    float v = (Y[e] - mu) * rsqrtf(var + 1e-5f) * g[f] + b[f];
    Y[e] = v > 0.f ? v : 0.f;
}

// Fused BN+ReLU (in place on Y) + 4:1 max pool into P. Y: (4*Nout, B, F)
__global__ void bn_pool_k(float* __restrict__ Y, float* __restrict__ P,
                          const float* __restrict__ g, const float* __restrict__ b,
                          int Nout, int F, float invM,
                          const float* __restrict__ sums, const float* __restrict__ sqs) {
    int t = blockIdx.x * blockDim.x + threadIdx.x;
    int total = Nout * BG * F;
    if (t >= total) return;
    int f = t % F; int rb = t / F; int bb = rb % BG; int n2 = rb / BG;
    float mu = sums[f] * invM;
    float var = sqs[f] * invM - mu * mu;
    float sc = rsqrtf(var + 1e-5f) * g[f];
    float sh = b[f] - mu * sc;
    size_t base = ((size_t)(n2 * 4) * BG + bb) * F + f;
    size_t stride = (size_t)BG * F;
    float m = -1e30f;
    #pragma unroll
    for (int i = 0; i < 4; i++) {
        float v = Y[base + i * stride] * sc + sh;
        v = v > 0.f ? v : 0.f;
        Y[base + i * stride] = v;
        m = fmaxf(m, v);
    }
    P[t] = m;
}

// Out layer projections: BN+ReLU(X row, d3 stats) then 4 dots with Horner weights.
__global__ void proj4_k(const float* __restrict__ X, const float* __restrict__ wc,
                        float* __restrict__ P, int M, size_t psz,
                        const float* __restrict__ g, const float* __restrict__ b,
                        float invM, const float* __restrict__ sums,
                        const float* __restrict__ sqs) {
    int gw = (int)((blockIdx.x * blockDim.x + threadIdx.x) >> 5);
    int lane = threadIdx.x & 31;
    if (gw >= M) return;
    float x = X[(size_t)gw * 32 + lane];
    float mu = sums[lane] * invM;
    float var = sqs[lane] * invM - mu * mu;
    float xb = (x - mu) * rsqrtf(var + 1e-5f) * g[lane] + b[lane];
    xb = xb > 0.f ? xb : 0.f;
    float a0 = xb * wc[lane * 4 + 0];
    float a1 = xb * wc[lane * 4 + 1];
    float a2 = xb * wc[lane * 4 + 2];
    float a3 = xb * wc[lane * 4 + 3];
    #pragma unroll
    for (int o = 16; o; o >>= 1) {
        a0 += __shfl_down_sync(0xffffffffu, a0, o);
        a1 += __shfl_down_sync(0xffffffffu, a1, o);
        a2 += __shfl_down_sync(0xffffffffu, a2, o);
        a3 += __shfl_down_sync(0xffffffffu, a3, o);
    }
    if (lane == 0) {
        P[gw] = a0; P[psz + gw] = a1; P[2 * psz + gw] = a2; P[3 * psz + gw] = a3;
    }
}

// Y layout row = n*256 + bg  ->  out (4,1,8,8,768)
__global__ void reshape_out_k(const float* __restrict__ Y, float* __restrict__ out) {
    int t = blockIdx.x * blockDim.x + threadIdx.x;
    int n = t % 768;
    int r = t / 768;
    int hw = r & 63;
    int b0 = r >> 6;
    out[t] = Y[(size_t)n * BG + (size_t)b0 * 64 + hw];
}

// ---------------- host side ----------------

extern "C" void kernel_launch(void* const* d_in, const int* in_sizes, int n_in,
                              void* d_out, int out_size) {
    const float* x = (const float*)d_in[0];

    float *A_, *B_, *Z_, *S3, *S2, *S1, *Wc, *sum_, *sq_, *cval;
    int *cidx, *cnnz;
    cudaGetSymbolAddress((void**)&A_,  g_A);
    cudaGetSymbolAddress((void**)&B_,  g_B);
    cudaGetSymbolAddress((void**)&Z_,  g_Z);
    cudaGetSymbolAddress((void**)&S3,  g_S3);
    cudaGetSymbolAddress((void**)&S2,  g_S2);
    cudaGetSymbolAddress((void**)&S1,  g_S1);
    cudaGetSymbolAddress((void**)&Wc,  g_Wc);
    cudaGetSymbolAddress((void**)&sum_, g_sum);
    cudaGetSymbolAddress((void**)&sq_,  g_sq);
    cudaGetSymbolAddress((void**)&cidx, g_cidx);
    cudaGetSymbolAddress((void**)&cval, g_cval);
    cudaGetSymbolAddress((void**)&cnnz, g_cnnz);

    const float* w_e3a = (const float*)d_in[5];
    const float* g_e3a_ = (const float*)d_in[6];  const float* b_e3a_ = (const float*)d_in[7];
    const float* w_e3b = (const float*)d_in[8];
    const float* g_e3b_ = (const float*)d_in[9];  const float* b_e3b_ = (const float*)d_in[10];
    const float* w_e2 = (const float*)d_in[11];
    const float* g_e2_ = (const float*)d_in[12];  const float* b_e2_ = (const float*)d_in[13];
    const float* w_e1 = (const float*)d_in[14];
    const float* g_e1_ = (const float*)d_in[15];  const float* b_e1_ = (const float*)d_in[16];
    const float* w_e0 = (const float*)d_in[17];
    const float* g_e0_ = (const float*)d_in[18];  const float* b_e0_ = (const float*)d_in[19];
    const float* w_d1 = (const float*)d_in[20];
    const float* g_d1_ = (const float*)d_in[21];  const float* b_d1_ = (const float*)d_in[22];
    const float* w_d2 = (const float*)d_in[23];
    const float* g_d2_ = (const float*)d_in[24];  const float* b_d2_ = (const float*)d_in[25];
    const float* w_d3 = (const float*)d_in[26];
    const float* g_d3_ = (const float*)d_in[27];  const float* b_d3_ = (const float*)d_in[28];
    const float* w_out = (const float*)d_in[29];

    zero_all_k<<<8, 256>>>(sum_, sq_);
    build_all_k<<<8, 128>>>((const float*)d_in[1], (const float*)d_in[2],
                            (const float*)d_in[3], (const float*)d_in[4],
                            cidx, cval, cnnz);
    wcomb_all_k<<<(86048 + 255) / 256, 256>>>(w_d1, w_d2, w_d3, w_out, Wc);
    transpose_in_k<<<6144, 256>>>(x, A_);

    auto spmm1 = [&](int lvl, int N, int F, const float* in, float* out,
                     float alpha, float beta, const float* S,
                     float* su, float* sq, int mask) {
        int cols4 = BG * F / 4;
        int thr = cols4 < 256 ? cols4 : 256;
        dim3 gs(cols4 / thr, N);
        spmm_k<<<gs, thr>>>(cidx + lvl * 768 * MAXNNZ, cval + lvl * 768 * MAXNNZ,
                            cnnz + lvl * 768, cols4, (const float4*)in, (float4*)out,
                            alpha, beta, (const float4*)S, su, sq, mask);
    };

    auto spmm3 = [&](int lvl, int N, int F, const float* in) {
        spmm1(lvl, N, F, in, Z_, 1.f, 0.f, nullptr, nullptr, nullptr, 0);
        spmm1(lvl, N, F, Z_, Z_ + SLICE, 2.f, -1.f, in, nullptr, nullptr, 0);
        spmm1(lvl, N, F, Z_ + SLICE, Z_ + 2 * SLICE, 2.f, -1.f, Z_, nullptr, nullptr, 0);
    };

    // plain (encoder) GEMM: 4 segments, Ktot = 4F
    auto run_tc = [&](const float* A0, const float* Zbp, const float* W, float* C,
                      int M, int F, int lgF, int No, float* su, float* sq) {
        int Ktot = 4 * F;
        if (No >= 128) {
            dim3 g(M / 128, No / 128);
            gemm_tc_k<128, 64, 32, false><<<g, 256>>>(A0, Zbp, W, C, F, lgF, No, su, sq,
                0, 0, 0, 0, nullptr, nullptr, nullptr, nullptr, 0.f, Ktot);
        } else if (No == 64) {
            gemm_tc_k<64, 32, 32, false><<<M / 128, 256>>>(A0, Zbp, W, C, F, lgF, No, su, sq,
                0, 0, 0, 0, nullptr, nullptr, nullptr, nullptr, 0.f, Ktot);
        } else {
            gemm_tc_k<32, 32, 16, false><<<M / 128, 256>>>(A0, Zbp, W, C, F, lgF, No, su, sq,
                0, 0, 0, 0, nullptr, nullptr, nullptr, nullptr, 0.f, Ktot);
        }
    };

    // -------- encoder --------
    // e3a (tc path, F=8), stats idx 0
    spmm3(0, 768, 8, A_);
    run_tc(A_, Z_, w_e3a, B_, 196608, 8, 3, 32, sum_ + 0, sq_ + 0);
    bn_apply_k<<<(196608 * 32 + 255) / 256, 256>>>(B_, g_e3a_, b_e3a_,
        (size_t)196608 * 32, 31, 1.0f / 196608.f, sum_ + 0, sq_ + 0);
    // e3b, stats idx 1
    spmm3(0, 768, 32, B_);
    run_tc(B_, Z_, w_e3b, S3, 196608, 32, 5, 64, sum_ + 256, sq_ + 256);
    bn_pool_k<<<(192 * BG * 64 + 255) / 256, 256>>>(S3, A_, g_e3b_, b_e3b_, 192, 64,
        1.0f / 196608.f, sum_ + 256, sq_ + 256);
    // e2, stats idx 2
    spmm3(1, 192, 64, A_);
    run_tc(A_, Z_, w_e2, S2, 49152, 64, 6, 128, sum_ + 512, sq_ + 512);
    bn_pool_k<<<(48 * BG * 128 + 255) / 256, 256>>>(S2, A_, g_e2_, b_e2_, 48, 128,
        1.0f / 49152.f, sum_ + 512, sq_ + 512);
    // e1, stats idx 3
    spmm3(2, 48, 128, A_);
    run_tc(A_, Z_, w_e1, S1, 12288, 128, 7, 256, sum_ + 768, sq_ + 768);
    bn_pool_k<<<(12 * BG * 256 + 255) / 256, 256>>>(S1, A_, g_e1_, b_e1_, 12, 256,
        1.0f / 12288.f, sum_ + 768, sq_ + 768);
    // e0, stats idx 4 (raw -> B_; BN applied inline in d1 GEMM staging)
    spmm3(3, 12, 256, A_);
    run_tc(A_, Z_, w_e0, B_, 3072, 256, 8, 256, sum_ + 1024, sq_ + 1024);

    // -------- decoder: concat GEMM (fused unpool+BN) + Horner spmm chain --------
    auto deco = [&](int lvl, int N, int Fu, int Fs, int Fo, const float* Wcp,
                    const float* H, const float* S,
                    const float* bg_, const float* bb_,
                    const float* bsum, const float* bsq, float binv,
                    float* out, float* su, float* sq) {
        int M = N * BG;
        size_t PS = (size_t)M * Fo;
        int F = Fu + Fs;
        int No = 4 * Fo;
        dim3 g(M / 128, No / 128);
        gemm_tc_k<128, 64, 32, true><<<g, 256>>>(H, S, Wcp, Z_, F, 0, No,
            nullptr, nullptr, Fo, PS, Fu, Fs, bg_, bb_, bsum, bsq, binv, F);
        spmm1(lvl, N, Fo, Z_,          Z_ + PS,     1.f, 1.f, Z_ + PS, nullptr, nullptr, 0);
        spmm1(lvl, N, Fo, Z_ + PS,     Z_ + 2 * PS, 1.f, 1.f, Z_ + 2 * PS, nullptr, nullptr, 0);
        spmm1(lvl, N, Fo, Z_ + 2 * PS, out,         1.f, 1.f, Z_ + 3 * PS, su, sq, Fo - 1);
    };

    // d1: H = e0 raw (B_, stats idx4), S = S1 -> out A_, stats idx 5
    deco(2, 48, 256, 256, 128, Wc + W1OFF, B_, S1,
         g_e0_, b_e0_, sum_ + 1024, sq_ + 1024, 1.0f / 3072.f,
         A_, sum_ + 1280, sq_ + 1280);
    // d2: H = d1 raw (A_, idx5), S = S2 -> out B_, stats idx 6
    deco(1, 192, 128, 128, 64, Wc + W2OFF, A_, S2,
         g_d1_, b_d1_, sum_ + 1280, sq_ + 1280, 1.0f / 12288.f,
         B_, sum_ + 1536, sq_ + 1536);
    // d3: H = d2 raw (B_, idx6), S = S3 -> out A_, stats idx 7
    deco(0, 768, 64, 64, 32, Wc + W3OFF, B_, S3,
         g_d2_, b_d2_, sum_ + 1536, sq_ + 1536, 1.0f / 49152.f,
         A_, sum_ + 1792, sq_ + 1792);

    // -------- out layer (32 -> 1), BN(d3) fused into projection --------
    {
        int M = 196608;
        size_t PS = (size_t)M;
        proj4_k<<<(M * 32 + 255) / 256, 256>>>(A_, Wc + W4OFF, Z_, M, PS,
            g_d3_, b_d3_, 1.0f / 196608.f, sum_ + 1792, sq_ + 1792);
        spmm1(0, 768, 1, Z_,          Z_ + PS,     1.f, 1.f, Z_ + PS, nullptr, nullptr, 0);
        spmm1(0, 768, 1, Z_ + PS,     Z_ + 2 * PS, 1.f, 1.f, Z_ + 2 * PS, nullptr, nullptr, 0);
        spmm1(0, 768, 1, Z_ + 2 * PS, B_,          1.f, 1.f, Z_ + 3 * PS, nullptr, nullptr, 0);
    }
    reshape_out_k<<<196608 / 256, 256>>>(B_, (float*)d_out);
}